// round 13
// baseline (speedup 1.0000x reference)
#include <cuda_runtime.h>
#include <cuda_bf16.h>
#include <math.h>
#include <stdint.h>

#define N_NODES 100000
#define N_EDGES 1600000
#define D_HID 128
#define D_OUT 32
#define SCAN_B 1024
#define TILES128 ((N_NODES + 63) / 64)   // 1563
#define GEMM_GRID 296
#define NA1 55040                         // L0 split (mult of 128)
#define TA1 (NA1 / 64)                    // 860
#define NA2 78976                         // L1 split (mult of 128)
#define TA2 (NA2 / 128)                   // 617

// ---------------- scratch ----------------
// g_yl/g_yr sized for fp32 [N,128]; bf16 [N,128] uses half -> two bf16 buffers each (A: base, B: +N*128 bf16)
__device__ float g_yl[(size_t)N_NODES * D_HID];
__device__ float g_yr[(size_t)N_NODES * D_HID];
__device__ float g_h0[(size_t)N_NODES * D_HID];
__device__ float g_invdeg[N_NODES];
__device__ int   g_cnt[N_NODES];
__device__ int   g_rowptr[N_NODES + 1];
__device__ int   g_fill[N_NODES];
__device__ int   g_srcs[N_EDGES];
__device__ int   g_bsum[(N_NODES + SCAN_B - 1) / SCAN_B];
__device__ int   g_boff[(N_NODES + SCAN_B - 1) / SCAN_B];
__device__ int   g_idx64;
__device__ uint32_t g_wp128[4][128 * 64];
__device__ uint32_t g_wp32[2][32 * 64];

// ---------------- helpers ----------------
__device__ __forceinline__ void mma_bf16(float c[4], const uint32_t a[4], const uint32_t b[2]) {
    asm volatile(
        "mma.sync.aligned.m16n8k16.row.col.f32.bf16.bf16.f32 "
        "{%0,%1,%2,%3}, {%4,%5,%6,%7}, {%8,%9}, {%0,%1,%2,%3};"
        : "+f"(c[0]), "+f"(c[1]), "+f"(c[2]), "+f"(c[3])
        : "r"(a[0]), "r"(a[1]), "r"(a[2]), "r"(a[3]), "r"(b[0]), "r"(b[1]));
}
__device__ __forceinline__ uint32_t pack_bf16(float a, float b) {
    __nv_bfloat162 p = __floats2bfloat162_rn(a, b);
    return *(uint32_t*)&p;
}
__device__ __forceinline__ void ldsm_x4(uint32_t r[4], uint32_t addr) {
    asm volatile("ldmatrix.sync.aligned.m8n8.x4.shared.b16 {%0,%1,%2,%3}, [%4];"
                 : "=r"(r[0]), "=r"(r[1]), "=r"(r[2]), "=r"(r[3]) : "r"(addr));
}
__device__ __forceinline__ void ldsm_x2(uint32_t r[2], uint32_t addr) {
    asm volatile("ldmatrix.sync.aligned.m8n8.x2.shared.b16 {%0,%1}, [%2];"
                 : "=r"(r[0]), "=r"(r[1]) : "r"(addr));
}
__device__ __forceinline__ uint32_t smem_u32(const void* p) {
    return (uint32_t)__cvta_generic_to_shared(p);
}
__device__ __forceinline__ void acc8(float a[8], uint4 u) {
    float2 f;
    f = __bfloat1622float2(*(__nv_bfloat162*)&u.x); a[0] += f.x; a[1] += f.y;
    f = __bfloat1622float2(*(__nv_bfloat162*)&u.y); a[2] += f.x; a[3] += f.y;
    f = __bfloat1622float2(*(__nv_bfloat162*)&u.z); a[4] += f.x; a[5] += f.y;
    f = __bfloat1622float2(*(__nv_bfloat162*)&u.w); a[6] += f.x; a[7] += f.y;
}

// ---------------- edge index access ----------------
__device__ __forceinline__ int edge_src(const void* __restrict__ ei, int e) {
    return g_idx64 ? (int)((const long long*)ei)[e] : ((const int*)ei)[e];
}
__device__ __forceinline__ int edge_dst(const void* __restrict__ ei, int e) {
    return g_idx64 ? (int)((const long long*)ei)[N_EDGES + e] : ((const int*)ei)[N_EDGES + e];
}

// ---------------- weight pre-pack ----------------
__global__ void pack_w_kernel(const float* __restrict__ Wl0, const float* __restrict__ Wr0,
                              const float* __restrict__ Wl1, const float* __restrict__ Wr1,
                              const float* __restrict__ Wl2, const float* __restrict__ Wr2) {
    int idx = blockIdx.x * blockDim.x + threadIdx.x;
    if (idx < 4 * 8192) {
        int mat = idx >> 13, r = idx & 8191;
        int kp = r >> 7, n = r & 127;
        const float* W = (mat == 0) ? Wl0 : (mat == 1) ? Wr0 : (mat == 2) ? Wl1 : Wr1;
        g_wp128[mat][n * 64 + kp] = pack_bf16(W[(2 * kp) * 128 + n], W[(2 * kp + 1) * 128 + n]);
    } else {
        int r2 = idx - 32768;
        if (r2 < 2 * 2048) {
            int mat = r2 >> 11, r = r2 & 2047;
            int kp = r >> 5, n = r & 31;
            const float* W = mat ? Wr2 : Wl2;
            g_wp32[mat][n * 64 + kp] = pack_bf16(W[(2 * kp) * 32 + n], W[(2 * kp + 1) * 32 + n]);
        }
    }
}

// ---------------- CSR build ----------------
__global__ void init_kernel(const int* __restrict__ ei32) {
    int i = blockIdx.x * blockDim.x + threadIdx.x;
    if (i == 0) {
        int all0 = 1;
#pragma unroll
        for (int k = 1; k < 64; k += 2) all0 &= (ei32[k] == 0);
        g_idx64 = all0;
    }
    if (i < N_NODES) g_cnt[i] = 0;
}
__global__ void hist_kernel(const void* __restrict__ ei) {
    int e = blockIdx.x * blockDim.x + threadIdx.x;
    if (e < N_EDGES) atomicAdd(&g_cnt[edge_dst(ei, e)], 1);
}
__global__ void scan_block_kernel() {
    __shared__ int sb[2][SCAN_B];
    int tid = threadIdx.x;
    int i = blockIdx.x * SCAN_B + tid;
    int v = (i < N_NODES) ? g_cnt[i] : 0;
    sb[0][tid] = v;
    int cur = 0;
#pragma unroll
    for (int d = 1; d < SCAN_B; d <<= 1) {
        __syncthreads();
        int nv = sb[cur][tid] + (tid >= d ? sb[cur][tid - d] : 0);
        sb[cur ^ 1][tid] = nv;
        cur ^= 1;
    }
    __syncthreads();
    if (i < N_NODES) g_rowptr[i + 1] = sb[cur][tid];
    if (tid == SCAN_B - 1) g_bsum[blockIdx.x] = sb[cur][tid];
    if (i == 0) g_rowptr[0] = 0;
}
__global__ void scan_bsum_kernel(int nblocks) {
    __shared__ int sm2[2][128];
    int tid = threadIdx.x;
    int v = (tid < nblocks) ? g_bsum[tid] : 0;
    sm2[0][tid] = v;
    int cur = 0;
#pragma unroll
    for (int d = 1; d < 128; d <<= 1) {
        __syncthreads();
        int nv = sm2[cur][tid] + (tid >= d ? sm2[cur][tid - d] : 0);
        sm2[cur ^ 1][tid] = nv;
        cur ^= 1;
    }
    __syncthreads();
    if (tid < nblocks) g_boff[tid] = sm2[cur][tid] - v;
}
__global__ void finalize_csr_kernel() {
    int i = blockIdx.x * blockDim.x + threadIdx.x;
    if (i >= N_NODES) return;
    int off = g_boff[i / SCAN_B];
    int end = g_rowptr[i + 1] + off;
    g_rowptr[i + 1] = end;
    int c = g_cnt[i];
    g_fill[i] = end - c;
    g_invdeg[i] = 1.0f / fmaxf((float)c, 1.0f);
}
__global__ void fill_kernel(const void* __restrict__ ei) {
    int e = blockIdx.x * blockDim.x + threadIdx.x;
    if (e >= N_EDGES) return;
    int d = edge_dst(ei, e);
    int pos = atomicAdd(&g_fill[d], 1);
    g_srcs[pos] = edge_src(ei, e);
}

// ---------------- persistent dual GEMM, DO=128, tile range [t0,t1) ----------------
template <typename TIN>
__launch_bounds__(256, 2)
__global__ void gemm128_dual_kernel(const TIN* __restrict__ X,
                                    const uint32_t* __restrict__ wpl, const uint32_t* __restrict__ wpr,
                                    __nv_bfloat16* __restrict__ Ylb, __nv_bfloat16* __restrict__ Yrb,
                                    int t0, int t1) {
    constexpr int S = 68;
    constexpr int ABUF = 64 * S;
    extern __shared__ uint32_t sm[];
    uint32_t* As0 = sm;
    uint32_t* As1 = sm + ABUF;
    uint32_t* Bls = sm + 2 * ABUF;
    uint32_t* Brs = Bls + 128 * S;

    const int t = threadIdx.x;
    const int w = t >> 5;
    const int lane = t & 31;
    const int g = lane >> 2, tg = lane & 3;

#pragma unroll
    for (int it = 0; it < 8; ++it) {
        int i4 = t + it * 256;
        int n = i4 >> 4, kp4 = (i4 & 15) * 4;
        *(uint4*)(Bls + n * S + kp4) = ((const uint4*)wpl)[i4];
        *(uint4*)(Brs + n * S + kp4) = ((const uint4*)wpr)[i4];
    }

    auto fill_A = [&](uint32_t* As, int m0) {
        if constexpr (sizeof(TIN) == 4) {
#pragma unroll
            for (int it = 0; it < 8; ++it) {
                int idx = t + it * 256;
                int row = idx >> 5, c4 = idx & 31;
                int gr  = m0 + row;
                float4 v = make_float4(0.f, 0.f, 0.f, 0.f);
                if (gr < N_NODES) v = *(const float4*)((const float*)X + (size_t)gr * 128 + c4 * 4);
                uint32_t* p = As + row * S + c4 * 2;
                p[0] = pack_bf16(v.x, v.y);
                p[1] = pack_bf16(v.z, v.w);
            }
        } else {
#pragma unroll
            for (int it = 0; it < 4; ++it) {
                int idx = t + it * 256;
                int row = idx >> 4, q = idx & 15;
                int gr  = m0 + row;
                uint4 v = make_uint4(0, 0, 0, 0);
                if (gr < N_NODES) v = ((const uint4*)X)[(size_t)gr * 16 + q];
                *(uint4*)(As + row * S + q * 4) = v;
            }
        }
    };

    if (t0 + (int)blockIdx.x < t1) fill_A(As0, (t0 + blockIdx.x) * 64);
    __syncthreads();

    const int mgrp = w & 1;
    const int ngrp = (w >> 1) & 1;
    const int isR  = w >> 2;
    const int mr = mgrp * 32;
    const int nb = ngrp * 64;

    const uint32_t a_lane_off = ((mr + (lane & 7) + ((lane >> 3) & 1) * 8) * S + ((lane >> 4) << 2)) * 4;
    const int l15 = lane & 15;
    const uint32_t b_lane = ((nb + (l15 & 7)) * S + ((l15 >> 3) << 2)) * 4;
    const uint32_t bs_base = smem_u32(isR ? Brs : Bls) + b_lane;
    const uint32_t as0 = smem_u32(As0);
    const uint32_t as1 = smem_u32(As1);
    __nv_bfloat16* Y = isR ? Yrb : Ylb;

    int buf = 0;
    for (int tile = t0 + blockIdx.x; tile < t1; tile += GEMM_GRID, buf ^= 1) {
        const int m0 = tile * 64;
        const uint32_t as_base = (buf ? as1 : as0) + a_lane_off;

        float acc[2][8][4];
#pragma unroll
        for (int m = 0; m < 2; ++m)
#pragma unroll
            for (int n = 0; n < 8; ++n)
#pragma unroll
                for (int q = 0; q < 4; ++q) acc[m][n][q] = 0.f;

#pragma unroll
        for (int kt = 0; kt < 8; ++kt) {
            const uint32_t kb = kt * 32;
            uint32_t a0[4], a1[4];
            ldsm_x4(a0, as_base + kb);
            ldsm_x4(a1, as_base + 16 * S * 4 + kb);
#pragma unroll
            for (int n = 0; n < 8; ++n) {
                uint32_t b[2];
                ldsm_x2(b, bs_base + n * (8 * S * 4) + kb);
                mma_bf16(acc[0][n], a0, b);
                mma_bf16(acc[1][n], a1, b);
            }
        }

        int nt = tile + GEMM_GRID;
        if (nt < t1) fill_A(buf ? As0 : As1, nt * 64);

#pragma unroll
        for (int m = 0; m < 2; ++m) {
            const int r0 = m0 + mr + m * 16 + g;
            const int r1 = r0 + 8;
#pragma unroll
            for (int n = 0; n < 8; ++n) {
                int col = nb + n * 8 + 2 * tg;
                if (r0 < N_NODES)
                    *(uint32_t*)((char*)Y + (size_t)r0 * 256 + col * 2) = pack_bf16(acc[m][n][0], acc[m][n][1]);
                if (r1 < N_NODES)
                    *(uint32_t*)((char*)Y + (size_t)r1 * 256 + col * 2) = pack_bf16(acc[m][n][2], acc[m][n][3]);
            }
        }
        __syncthreads();
    }
}

// ---------------- dual GEMM, DO=32, row offset ----------------
__launch_bounds__(256, 2)
__global__ void gemm32_dual_kernel(const __nv_bfloat16* __restrict__ X,
                                   const uint32_t* __restrict__ wpl, const uint32_t* __restrict__ wpr,
                                   __nv_bfloat16* __restrict__ Ylb, float* __restrict__ Yr, int tile0) {
    constexpr int S = 68;
    extern __shared__ uint32_t sm[];
    uint32_t* As  = sm;
    uint32_t* Bls = sm + 128 * S;
    uint32_t* Brs = Bls + 32 * S;

    const int t = threadIdx.x;
    const int w = t >> 5;
    const int lane = t & 31;
    const int g = lane >> 2, tg = lane & 3;
    const int m0 = (tile0 + blockIdx.x) * 128;

#pragma unroll
    for (int it = 0; it < 8; ++it) {
        int idx = t + it * 256;
        int row = idx >> 4, q = idx & 15;
        int gr  = m0 + row;
        uint4 v = make_uint4(0, 0, 0, 0);
        if (gr < N_NODES) v = ((const uint4*)X)[(size_t)gr * 16 + q];
        *(uint4*)(As + row * S + q * 4) = v;
    }
#pragma unroll
    for (int it = 0; it < 2; ++it) {
        int i4 = t + it * 256;
        int n = i4 >> 4, kp4 = (i4 & 15) * 4;
        *(uint4*)(Bls + n * S + kp4) = ((const uint4*)wpl)[i4];
        *(uint4*)(Brs + n * S + kp4) = ((const uint4*)wpr)[i4];
    }
    __syncthreads();

    const int mr = w * 16;
    float accl[4][4], accr[4][4];
#pragma unroll
    for (int n = 0; n < 4; ++n)
#pragma unroll
        for (int q = 0; q < 4; ++q) { accl[n][q] = 0.f; accr[n][q] = 0.f; }

#pragma unroll
    for (int kt = 0; kt < 8; ++kt) {
        const int kb = kt * 8;
        uint32_t a[4];
        a[0] = As[(mr + g)     * S + kb + tg];
        a[1] = As[(mr + g + 8) * S + kb + tg];
        a[2] = As[(mr + g)     * S + kb + tg + 4];
        a[3] = As[(mr + g + 8) * S + kb + tg + 4];
#pragma unroll
        for (int n = 0; n < 4; ++n) {
            int col = n * 8 + g;
            uint32_t bl[2], br[2];
            bl[0] = Bls[col * S + kb + tg];
            bl[1] = Bls[col * S + kb + tg + 4];
            br[0] = Brs[col * S + kb + tg];
            br[1] = Brs[col * S + kb + tg + 4];
            mma_bf16(accl[n], a, bl);
            mma_bf16(accr[n], a, br);
        }
    }

    const int r0 = m0 + mr + g;
    const int r1 = r0 + 8;
#pragma unroll
    for (int n = 0; n < 4; ++n) {
        int col = n * 8 + 2 * tg;
        if (r0 < N_NODES) {
            *(uint32_t*)((char*)Ylb + (size_t)r0 * 64 + col * 2) = pack_bf16(accl[n][0], accl[n][1]);
            *(float2*)(Yr + (size_t)r0 * 32 + col) = make_float2(accr[n][0], accr[n][1]);
        }
        if (r1 < N_NODES) {
            *(uint32_t*)((char*)Ylb + (size_t)r1 * 64 + col * 2) = pack_bf16(accl[n][2], accl[n][3]);
            *(float2*)(Yr + (size_t)r1 * 32 + col) = make_float2(accr[n][2], accr[n][3]);
        }
    }
}

// ---------------- aggregation: warp/node, node range [n0,n1) ----------------
__global__ void agg_relu_kernel(const __nv_bfloat16* __restrict__ ylb, const __nv_bfloat16* __restrict__ yrb,
                                const float* __restrict__ bl, __nv_bfloat16* __restrict__ hb,
                                int n0, int n1) {
    int node = n0 + blockIdx.x * (blockDim.x >> 5) + (threadIdx.x >> 5);
    if (node >= n1) return;
    int lane = threadIdx.x & 31;
    int g2 = lane >> 4;
    int p  = lane & 15;
    int beg = g_rowptr[node], end = g_rowptr[node + 1];
    float a[8] = {0.f, 0.f, 0.f, 0.f, 0.f, 0.f, 0.f, 0.f};
    int j = beg;
    for (; j + 8 <= end; j += 8) {
        uint4 u[4];
#pragma unroll
        for (int q = 0; q < 4; ++q) {
            int s = __ldg(&g_srcs[j + 2 * q + g2]);
            u[q] = *(const uint4*)((const char*)ylb + (size_t)s * 256 + p * 16);
        }
#pragma unroll
        for (int q = 0; q < 4; ++q) acc8(a, u[q]);
    }
    for (; j + 2 <= end; j += 2) {
        int s = __ldg(&g_srcs[j + g2]);
        uint4 u = *(const uint4*)((const char*)ylb + (size_t)s * 256 + p * 16);
        acc8(a, u);
    }
    if (j < end && g2 == 0) {
        int s = __ldg(&g_srcs[j]);
        uint4 u = *(const uint4*)((const char*)ylb + (size_t)s * 256 + p * 16);
        acc8(a, u);
    }
#pragma unroll
    for (int i = 0; i < 8; ++i) a[i] += __shfl_xor_sync(0xFFFFFFFFu, a[i], 16);

    if (g2 == 0) {
        float id = g_invdeg[node];
        uint4 ur = *(const uint4*)((const char*)yrb + (size_t)node * 256 + p * 16);
        float2 r01 = __bfloat1622float2(*(__nv_bfloat162*)&ur.x);
        float2 r23 = __bfloat1622float2(*(__nv_bfloat162*)&ur.y);
        float2 r45 = __bfloat1622float2(*(__nv_bfloat162*)&ur.z);
        float2 r67 = __bfloat1622float2(*(__nv_bfloat162*)&ur.w);
        float4 b0 = ((const float4*)bl)[2 * p];
        float4 b1 = ((const float4*)bl)[2 * p + 1];
        float o0 = fmaxf(fmaf(a[0], id, b0.x) + r01.x, 0.f);
        float o1 = fmaxf(fmaf(a[1], id, b0.y) + r01.y, 0.f);
        float o2 = fmaxf(fmaf(a[2], id, b0.z) + r23.x, 0.f);
        float o3 = fmaxf(fmaf(a[3], id, b0.w) + r23.y, 0.f);
        float o4 = fmaxf(fmaf(a[4], id, b1.x) + r45.x, 0.f);
        float o5 = fmaxf(fmaf(a[5], id, b1.y) + r45.y, 0.f);
        float o6 = fmaxf(fmaf(a[6], id, b1.z) + r67.x, 0.f);
        float o7 = fmaxf(fmaf(a[7], id, b1.w) + r67.y, 0.f);
        uint4 ov = make_uint4(pack_bf16(o0, o1), pack_bf16(o2, o3),
                              pack_bf16(o4, o5), pack_bf16(o6, o7));
        *(uint4*)((char*)hb + (size_t)node * 256 + p * 16) = ov;
    }
}

// log_softmax layer
__global__ void agg_lsm_kernel(const __nv_bfloat16* __restrict__ ylb, const float* __restrict__ yr,
                               const float* __restrict__ bl2, float* __restrict__ out) {
    int node = blockIdx.x * (blockDim.x >> 5) + (threadIdx.x >> 5);
    if (node >= N_NODES) return;
    int lane = threadIdx.x & 31;
    int g2 = lane >> 4;
    int p  = lane & 15;
    int beg = g_rowptr[node], end = g_rowptr[node + 1];
    float ax = 0.f, ay = 0.f;
    const uint32_t* yl32 = (const uint32_t*)ylb;
    int j = beg;
    for (; j + 4 <= end; j += 4) {
        int sA = __ldg(&g_srcs[j + g2]);
        int sB = __ldg(&g_srcs[j + 2 + g2]);
        uint32_t uA = __ldg(&yl32[(size_t)sA * 16 + p]);
        uint32_t uB = __ldg(&yl32[(size_t)sB * 16 + p]);
        float2 fA = __bfloat1622float2(*(__nv_bfloat162*)&uA);
        float2 fB = __bfloat1622float2(*(__nv_bfloat162*)&uB);
        ax += fA.x + fB.x; ay += fA.y + fB.y;
    }
    if (j + 2 <= end) {
        int s = __ldg(&g_srcs[j + g2]);
        uint32_t u = __ldg(&yl32[(size_t)s * 16 + p]);
        float2 f = __bfloat1622float2(*(__nv_bfloat162*)&u);
        ax += f.x; ay += f.y;
        j += 2;
    }
    if (j < end && g2 == 0) {
        int s = __ldg(&g_srcs[j]);
        uint32_t u = __ldg(&yl32[(size_t)s * 16 + p]);
        float2 f = __bfloat1622float2(*(__nv_bfloat162*)&u);
        ax += f.x; ay += f.y;
    }
    ax += __shfl_xor_sync(0xFFFFFFFFu, ax, 16);
    ay += __shfl_xor_sync(0xFFFFFFFFu, ay, 16);

    float id = g_invdeg[node];
    float2 b2 = ((const float2*)bl2)[p];
    float2 r2 = ((const float2*)yr)[(size_t)node * 16 + p];
    float v0 = fmaf(ax, id, b2.x) + r2.x;
    float v1 = fmaf(ay, id, b2.y) + r2.y;
    float m = fmaxf(v0, v1);
#pragma unroll
    for (int o = 1; o < 16; o <<= 1) m = fmaxf(m, __shfl_xor_sync(0xFFFFFFFFu, m, o));
    float s = expf(v0 - m) + expf(v1 - m);
#pragma unroll
    for (int o = 1; o < 16; o <<= 1) s += __shfl_xor_sync(0xFFFFFFFFu, s, o);
    float ls = logf(s);
    if (g2 == 0)
        ((float2*)out)[(size_t)node * 16 + p] = make_float2(v0 - m - ls, v1 - m - ls);
}

// ---------------- host ----------------
extern "C" void kernel_launch(void* const* d_in, const int* in_sizes, int n_in,
                              void* d_out, int out_size) {
    const float* x   = (const float*)d_in[0];
    const void*  ei  = d_in[1];
    const float* Wl0 = (const float*)d_in[2];
    const float* bl0 = (const float*)d_in[3];
    const float* Wr0 = (const float*)d_in[4];
    const float* Wl1 = (const float*)d_in[5];
    const float* bl1 = (const float*)d_in[6];
    const float* Wr1 = (const float*)d_in[7];
    const float* Wl2 = (const float*)d_in[8];
    const float* bl2 = (const float*)d_in[9];
    const float* Wr2 = (const float*)d_in[10];
    float* out = (float*)d_out;

    float *yl, *yr, *h0;
    uint32_t *wp128, *wp32;
    cudaGetSymbolAddress((void**)&yl, g_yl);
    cudaGetSymbolAddress((void**)&yr, g_yr);
    cudaGetSymbolAddress((void**)&h0, g_h0);
    cudaGetSymbolAddress((void**)&wp128, g_wp128);
    cudaGetSymbolAddress((void**)&wp32, g_wp32);
    // double bf16 buffers within the fp32-sized arrays
    __nv_bfloat16* ylbA = (__nv_bfloat16*)yl;
    __nv_bfloat16* ylbB = ylbA + (size_t)N_NODES * 128;
    __nv_bfloat16* yrbA = (__nv_bfloat16*)yr;
    __nv_bfloat16* yrbB = yrbA + (size_t)N_NODES * 128;
    __nv_bfloat16* h0b  = (__nv_bfloat16*)h0;

    static cudaStream_t s2 = nullptr;
    static cudaEvent_t ev_fork = nullptr, ev_join = nullptr, evA = nullptr, evB = nullptr,
                       evC = nullptr, evD = nullptr;
    if (!s2) {
        cudaStreamCreateWithFlags(&s2, cudaStreamNonBlocking);
        cudaEventCreateWithFlags(&ev_fork, cudaEventDisableTiming);
        cudaEventCreateWithFlags(&ev_join, cudaEventDisableTiming);
        cudaEventCreateWithFlags(&evA, cudaEventDisableTiming);
        cudaEventCreateWithFlags(&evB, cudaEventDisableTiming);
        cudaEventCreateWithFlags(&evC, cudaEventDisableTiming);
        cudaEventCreateWithFlags(&evD, cudaEventDisableTiming);
    }

    const int SMEM128 = (2 * 64 * 68 + 2 * 128 * 68) * 4;
    const int SMEM32  = (128 * 68 + 2 * 32 * 68) * 4;
    cudaFuncSetAttribute(gemm128_dual_kernel<float>, cudaFuncAttributeMaxDynamicSharedMemorySize, SMEM128);
    cudaFuncSetAttribute(gemm128_dual_kernel<__nv_bfloat16>, cudaFuncAttributeMaxDynamicSharedMemorySize, SMEM128);
    cudaFuncSetAttribute(gemm32_dual_kernel, cudaFuncAttributeMaxDynamicSharedMemorySize, SMEM32);

    const int T = 256;
    const int NB = (N_NODES + T - 1) / T;
    const int EB = (N_EDGES + T - 1) / T;
    const int SCB = (N_NODES + SCAN_B - 1) / SCAN_B;
    const int GT32 = (N_NODES + 127) / 128;   // 782

    auto aggB = [](int n0, int n1) { return (n1 - n0 + 7) / 8; };

    // ---- front: CSR on s2 overlapped with pack + layer-0 GEMM on main ----
    cudaEventRecord(ev_fork, 0);
    cudaStreamWaitEvent(s2, ev_fork, 0);

    init_kernel<<<NB, T, 0, s2>>>((const int*)ei);
    pack_w_kernel<<<144, 256>>>(Wl0, Wr0, Wl1, Wr1, Wl2, Wr2);
    hist_kernel<<<EB, T, 0, s2>>>(ei);
    gemm128_dual_kernel<float><<<GEMM_GRID, 256, SMEM128>>>(x, wp128, wp128 + 8192, ylbA, yrbA, 0, TILES128);
    scan_block_kernel<<<SCB, SCAN_B, 0, s2>>>();
    scan_bsum_kernel<<<1, 128, 0, s2>>>(SCB);
    finalize_csr_kernel<<<NB, T, 0, s2>>>();
    fill_kernel<<<EB, T, 0, s2>>>(ei);
    cudaEventRecord(ev_join, s2);
    cudaStreamWaitEvent(0, ev_join, 0);

    // ---- Layer 0 agg (reads A buffers) overlapped with Layer 1 GEMM (writes B buffers) ----
    agg_relu_kernel<<<aggB(0, NA1), T>>>(ylbA, yrbA, bl0, h0b, 0, NA1);
    cudaEventRecord(evA, 0);
    cudaStreamWaitEvent(s2, evA, 0);
    agg_relu_kernel<<<aggB(NA1, N_NODES), T, 0, s2>>>(ylbA, yrbA, bl0, h0b, NA1, N_NODES);
    cudaEventRecord(evB, s2);

    gemm128_dual_kernel<__nv_bfloat16><<<GEMM_GRID, 256, SMEM128>>>(
        h0b, wp128 + 2 * 8192, wp128 + 3 * 8192, ylbB, yrbB, 0, TA1);
    cudaStreamWaitEvent(0, evB, 0);
    gemm128_dual_kernel<__nv_bfloat16><<<GEMM_GRID, 256, SMEM128>>>(
        h0b, wp128 + 2 * 8192, wp128 + 3 * 8192, ylbB, yrbB, TA1, TILES128);

    // ---- Layer 1 agg (reads B buffers) overlapped with Layer 2 GEMM (writes A-base, disjoint) ----
    agg_relu_kernel<<<aggB(0, NA2), T>>>(ylbB, yrbB, bl1, h0b, 0, NA2);
    cudaEventRecord(evC, 0);
    cudaStreamWaitEvent(s2, evC, 0);
    agg_relu_kernel<<<aggB(NA2, N_NODES), T, 0, s2>>>(ylbB, yrbB, bl1, h0b, NA2, N_NODES);
    cudaEventRecord(evD, s2);

    gemm32_dual_kernel<<<TA2, T, SMEM32>>>(h0b, wp32, wp32 + 2048, ylbA, yr, 0);
    cudaStreamWaitEvent(0, evD, 0);
    gemm32_dual_kernel<<<GT32 - TA2, T, SMEM32>>>(h0b, wp32, wp32 + 2048, ylbA, yr, TA2);

    // ---- final log_softmax (reads ylbA 32-wide + yr fp32) ----
    agg_lsm_kernel<<<(N_NODES + 7) / 8, T>>>(ylbA, yr, bl2, out);
}

// round 14
// speedup vs baseline: 1.1221x; 1.1221x over previous
#include <cuda_runtime.h>
#include <cuda_bf16.h>
#include <cuda_fp16.h>
#include <math.h>
#include <stdint.h>

#define N_NODES 100000
#define N_EDGES 1600000
#define D_HID 128
#define D_OUT 32
#define SCAN_B 1024
#define TILES128 ((N_NODES + 63) / 64)   // 1563
#define GEMM_GRID 296

// ---------------- scratch ----------------
__device__ float g_yl[(size_t)N_NODES * D_HID];   // L0/L1: fp8 [N,128]; L2: bf16 [N,32]
__device__ float g_yr[(size_t)N_NODES * D_HID];   // L0/L1: bf16 [N,128]; L2: fp32 [N,32]
__device__ float g_h0[(size_t)N_NODES * D_HID];   // bf16 [N,128] activations
__device__ float g_invdeg[N_NODES];
__device__ int   g_cnt[N_NODES];
__device__ int   g_rowptr[N_NODES + 1];
__device__ int   g_fill[N_NODES];
__device__ int   g_srcs[N_EDGES];
__device__ int   g_bsum[(N_NODES + SCAN_B - 1) / SCAN_B];
__device__ int   g_boff[(N_NODES + SCAN_B - 1) / SCAN_B];
__device__ int   g_idx64;
__device__ uint32_t g_wp128[4][128 * 64];
__device__ uint32_t g_wp32[2][32 * 64];

// ---------------- helpers ----------------
__device__ __forceinline__ void mma_bf16(float c[4], const uint32_t a[4], const uint32_t b[2]) {
    asm volatile(
        "mma.sync.aligned.m16n8k16.row.col.f32.bf16.bf16.f32 "
        "{%0,%1,%2,%3}, {%4,%5,%6,%7}, {%8,%9}, {%0,%1,%2,%3};"
        : "+f"(c[0]), "+f"(c[1]), "+f"(c[2]), "+f"(c[3])
        : "r"(a[0]), "r"(a[1]), "r"(a[2]), "r"(a[3]), "r"(b[0]), "r"(b[1]));
}
__device__ __forceinline__ uint32_t pack_bf16(float a, float b) {
    __nv_bfloat162 p = __floats2bfloat162_rn(a, b);
    return *(uint32_t*)&p;
}
// pack two fp32 -> e4m3x2 (lo = a, hi = b)
__device__ __forceinline__ uint16_t pack_e4m3(float a, float b) {
    uint16_t r;
    asm("cvt.rn.satfinite.e4m3x2.f32 %0, %1, %2;" : "=h"(r) : "f"(b), "f"(a));
    return r;
}
// e4m3x2 -> half2 (lo byte -> lo half)
__device__ __forceinline__ uint32_t fp8x2_to_h2(uint32_t v) {
    uint32_t r;
    asm("cvt.rn.f16x2.e4m3x2 %0, %1;" : "=r"(r) : "h"((uint16_t)v));
    return r;
}
__device__ __forceinline__ uint32_t hadd2(uint32_t a, uint32_t b) {
    uint32_t r;
    asm("add.f16x2 %0, %1, %2;" : "=r"(r) : "r"(a), "r"(b));
    return r;
}
__device__ __forceinline__ float2 h2f2(uint32_t h) {
    __half2 v = *(__half2*)&h;
    return __half22float2(v);
}
__device__ __forceinline__ void ldsm_x4(uint32_t r[4], uint32_t addr) {
    asm volatile("ldmatrix.sync.aligned.m8n8.x4.shared.b16 {%0,%1,%2,%3}, [%4];"
                 : "=r"(r[0]), "=r"(r[1]), "=r"(r[2]), "=r"(r[3]) : "r"(addr));
}
__device__ __forceinline__ void ldsm_x2(uint32_t r[2], uint32_t addr) {
    asm volatile("ldmatrix.sync.aligned.m8n8.x2.shared.b16 {%0,%1}, [%2];"
                 : "=r"(r[0]), "=r"(r[1]) : "r"(addr));
}
__device__ __forceinline__ uint32_t smem_u32(const void* p) {
    return (uint32_t)__cvta_generic_to_shared(p);
}

// ---------------- edge index access ----------------
__device__ __forceinline__ int edge_src(const void* __restrict__ ei, int e) {
    return g_idx64 ? (int)((const long long*)ei)[e] : ((const int*)ei)[e];
}
__device__ __forceinline__ int edge_dst(const void* __restrict__ ei, int e) {
    return g_idx64 ? (int)((const long long*)ei)[N_EDGES + e] : ((const int*)ei)[N_EDGES + e];
}

// ---------------- weight pre-pack ----------------
__global__ void pack_w_kernel(const float* __restrict__ Wl0, const float* __restrict__ Wr0,
                              const float* __restrict__ Wl1, const float* __restrict__ Wr1,
                              const float* __restrict__ Wl2, const float* __restrict__ Wr2) {
    int idx = blockIdx.x * blockDim.x + threadIdx.x;
    if (idx < 4 * 8192) {
        int mat = idx >> 13, r = idx & 8191;
        int kp = r >> 7, n = r & 127;
        const float* W = (mat == 0) ? Wl0 : (mat == 1) ? Wr0 : (mat == 2) ? Wl1 : Wr1;
        g_wp128[mat][n * 64 + kp] = pack_bf16(W[(2 * kp) * 128 + n], W[(2 * kp + 1) * 128 + n]);
    } else {
        int r2 = idx - 32768;
        if (r2 < 2 * 2048) {
            int mat = r2 >> 11, r = r2 & 2047;
            int kp = r >> 5, n = r & 31;
            const float* W = mat ? Wr2 : Wl2;
            g_wp32[mat][n * 64 + kp] = pack_bf16(W[(2 * kp) * 32 + n], W[(2 * kp + 1) * 32 + n]);
        }
    }
}

// ---------------- CSR build ----------------
__global__ void init_kernel(const int* __restrict__ ei32) {
    int i = blockIdx.x * blockDim.x + threadIdx.x;
    if (i == 0) {
        int all0 = 1;
#pragma unroll
        for (int k = 1; k < 64; k += 2) all0 &= (ei32[k] == 0);
        g_idx64 = all0;
    }
    if (i < N_NODES) g_cnt[i] = 0;
}
__global__ void hist_kernel(const void* __restrict__ ei) {
    int e = blockIdx.x * blockDim.x + threadIdx.x;
    if (e < N_EDGES) atomicAdd(&g_cnt[edge_dst(ei, e)], 1);
}
__global__ void scan_block_kernel() {
    __shared__ int sb[2][SCAN_B];
    int tid = threadIdx.x;
    int i = blockIdx.x * SCAN_B + tid;
    int v = (i < N_NODES) ? g_cnt[i] : 0;
    sb[0][tid] = v;
    int cur = 0;
#pragma unroll
    for (int d = 1; d < SCAN_B; d <<= 1) {
        __syncthreads();
        int nv = sb[cur][tid] + (tid >= d ? sb[cur][tid - d] : 0);
        sb[cur ^ 1][tid] = nv;
        cur ^= 1;
    }
    __syncthreads();
    if (i < N_NODES) g_rowptr[i + 1] = sb[cur][tid];
    if (tid == SCAN_B - 1) g_bsum[blockIdx.x] = sb[cur][tid];
    if (i == 0) g_rowptr[0] = 0;
}
__global__ void scan_bsum_kernel(int nblocks) {
    __shared__ int sm2[2][128];
    int tid = threadIdx.x;
    int v = (tid < nblocks) ? g_bsum[tid] : 0;
    sm2[0][tid] = v;
    int cur = 0;
#pragma unroll
    for (int d = 1; d < 128; d <<= 1) {
        __syncthreads();
        int nv = sm2[cur][tid] + (tid >= d ? sm2[cur][tid - d] : 0);
        sm2[cur ^ 1][tid] = nv;
        cur ^= 1;
    }
    __syncthreads();
    if (tid < nblocks) g_boff[tid] = sm2[cur][tid] - v;
}
__global__ void finalize_csr_kernel() {
    int i = blockIdx.x * blockDim.x + threadIdx.x;
    if (i >= N_NODES) return;
    int off = g_boff[i / SCAN_B];
    int end = g_rowptr[i + 1] + off;
    g_rowptr[i + 1] = end;
    int c = g_cnt[i];
    g_fill[i] = end - c;
    g_invdeg[i] = 1.0f / fmaxf((float)c, 1.0f);
}
__global__ void fill_kernel(const void* __restrict__ ei) {
    int e = blockIdx.x * blockDim.x + threadIdx.x;
    if (e >= N_EDGES) return;
    int d = edge_dst(ei, e);
    int pos = atomicAdd(&g_fill[d], 1);
    g_srcs[pos] = edge_src(ei, e);
}

// ---------------- persistent dual GEMM, DO=128: Yl fp8, Yr bf16 ----------------
template <typename TIN>
__launch_bounds__(256, 2)
__global__ void gemm128_dual_kernel(const TIN* __restrict__ X,
                                    const uint32_t* __restrict__ wpl, const uint32_t* __restrict__ wpr,
                                    uint8_t* __restrict__ Ylq, __nv_bfloat16* __restrict__ Yrb) {
    constexpr int S = 68;
    constexpr int ABUF = 64 * S;
    extern __shared__ uint32_t sm[];
    uint32_t* As0 = sm;
    uint32_t* As1 = sm + ABUF;
    uint32_t* Bls = sm + 2 * ABUF;
    uint32_t* Brs = Bls + 128 * S;

    const int t = threadIdx.x;
    const int w = t >> 5;
    const int lane = t & 31;
    const int g = lane >> 2, tg = lane & 3;

#pragma unroll
    for (int it = 0; it < 8; ++it) {
        int i4 = t + it * 256;
        int n = i4 >> 4, kp4 = (i4 & 15) * 4;
        *(uint4*)(Bls + n * S + kp4) = ((const uint4*)wpl)[i4];
        *(uint4*)(Brs + n * S + kp4) = ((const uint4*)wpr)[i4];
    }

    auto fill_A = [&](uint32_t* As, int m0) {
        if constexpr (sizeof(TIN) == 4) {
#pragma unroll
            for (int it = 0; it < 8; ++it) {
                int idx = t + it * 256;
                int row = idx >> 5, c4 = idx & 31;
                int gr  = m0 + row;
                float4 v = make_float4(0.f, 0.f, 0.f, 0.f);
                if (gr < N_NODES) v = *(const float4*)((const float*)X + (size_t)gr * 128 + c4 * 4);
                uint32_t* p = As + row * S + c4 * 2;
                p[0] = pack_bf16(v.x, v.y);
                p[1] = pack_bf16(v.z, v.w);
            }
        } else {
#pragma unroll
            for (int it = 0; it < 4; ++it) {
                int idx = t + it * 256;
                int row = idx >> 4, q = idx & 15;
                int gr  = m0 + row;
                uint4 v = make_uint4(0, 0, 0, 0);
                if (gr < N_NODES) v = ((const uint4*)X)[(size_t)gr * 16 + q];
                *(uint4*)(As + row * S + q * 4) = v;
            }
        }
    };

    if ((int)blockIdx.x < TILES128) fill_A(As0, blockIdx.x * 64);
    __syncthreads();

    const int mgrp = w & 1;
    const int ngrp = (w >> 1) & 1;
    const int isR  = w >> 2;
    const int mr = mgrp * 32;
    const int nb = ngrp * 64;

    const uint32_t a_lane_off = ((mr + (lane & 7) + ((lane >> 3) & 1) * 8) * S + ((lane >> 4) << 2)) * 4;
    const int l15 = lane & 15;
    const uint32_t b_lane = ((nb + (l15 & 7)) * S + ((l15 >> 3) << 2)) * 4;
    const uint32_t bs_base = smem_u32(isR ? Brs : Bls) + b_lane;
    const uint32_t as0 = smem_u32(As0);
    const uint32_t as1 = smem_u32(As1);

    int buf = 0;
    for (int tile = blockIdx.x; tile < TILES128; tile += GEMM_GRID, buf ^= 1) {
        const int m0 = tile * 64;
        const uint32_t as_base = (buf ? as1 : as0) + a_lane_off;

        float acc[2][8][4];
#pragma unroll
        for (int m = 0; m < 2; ++m)
#pragma unroll
            for (int n = 0; n < 8; ++n)
#pragma unroll
                for (int q = 0; q < 4; ++q) acc[m][n][q] = 0.f;

#pragma unroll
        for (int kt = 0; kt < 8; ++kt) {
            const uint32_t kb = kt * 32;
            uint32_t a0[4], a1[4];
            ldsm_x4(a0, as_base + kb);
            ldsm_x4(a1, as_base + 16 * S * 4 + kb);
#pragma unroll
            for (int n = 0; n < 8; ++n) {
                uint32_t b[2];
                ldsm_x2(b, bs_base + n * (8 * S * 4) + kb);
                mma_bf16(acc[0][n], a0, b);
                mma_bf16(acc[1][n], a1, b);
            }
        }

        int nt = tile + GEMM_GRID;
        if (nt < TILES128) fill_A(buf ? As0 : As1, nt * 64);

#pragma unroll
        for (int m = 0; m < 2; ++m) {
            const int r0 = m0 + mr + m * 16 + g;
            const int r1 = r0 + 8;
#pragma unroll
            for (int n = 0; n < 8; ++n) {
                int col = nb + n * 8 + 2 * tg;
                if (!isR) {
                    if (r0 < N_NODES)
                        *(uint16_t*)(Ylq + (size_t)r0 * 128 + col) = pack_e4m3(acc[m][n][0], acc[m][n][1]);
                    if (r1 < N_NODES)
                        *(uint16_t*)(Ylq + (size_t)r1 * 128 + col) = pack_e4m3(acc[m][n][2], acc[m][n][3]);
                } else {
                    if (r0 < N_NODES)
                        *(uint32_t*)((char*)Yrb + (size_t)r0 * 256 + col * 2) = pack_bf16(acc[m][n][0], acc[m][n][1]);
                    if (r1 < N_NODES)
                        *(uint32_t*)((char*)Yrb + (size_t)r1 * 256 + col * 2) = pack_bf16(acc[m][n][2], acc[m][n][3]);
                }
            }
        }
        __syncthreads();
    }
}

// ---------------- dual GEMM, DO=32: Yl bf16, Yr fp32 ----------------
__launch_bounds__(256, 2)
__global__ void gemm32_dual_kernel(const __nv_bfloat16* __restrict__ X,
                                   const uint32_t* __restrict__ wpl, const uint32_t* __restrict__ wpr,
                                   __nv_bfloat16* __restrict__ Ylb, float* __restrict__ Yr) {
    constexpr int S = 68;
    extern __shared__ uint32_t sm[];
    uint32_t* As  = sm;
    uint32_t* Bls = sm + 128 * S;
    uint32_t* Brs = Bls + 32 * S;

    const int t = threadIdx.x;
    const int w = t >> 5;
    const int lane = t & 31;
    const int g = lane >> 2, tg = lane & 3;
    const int m0 = blockIdx.x * 128;

#pragma unroll
    for (int it = 0; it < 8; ++it) {
        int idx = t + it * 256;
        int row = idx >> 4, q = idx & 15;
        int gr  = m0 + row;
        uint4 v = make_uint4(0, 0, 0, 0);
        if (gr < N_NODES) v = ((const uint4*)X)[(size_t)gr * 16 + q];
        *(uint4*)(As + row * S + q * 4) = v;
    }
#pragma unroll
    for (int it = 0; it < 2; ++it) {
        int i4 = t + it * 256;
        int n = i4 >> 4, kp4 = (i4 & 15) * 4;
        *(uint4*)(Bls + n * S + kp4) = ((const uint4*)wpl)[i4];
        *(uint4*)(Brs + n * S + kp4) = ((const uint4*)wpr)[i4];
    }
    __syncthreads();

    const int mr = w * 16;
    float accl[4][4], accr[4][4];
#pragma unroll
    for (int n = 0; n < 4; ++n)
#pragma unroll
        for (int q = 0; q < 4; ++q) { accl[n][q] = 0.f; accr[n][q] = 0.f; }

#pragma unroll
    for (int kt = 0; kt < 8; ++kt) {
        const int kb = kt * 8;
        uint32_t a[4];
        a[0] = As[(mr + g)     * S + kb + tg];
        a[1] = As[(mr + g + 8) * S + kb + tg];
        a[2] = As[(mr + g)     * S + kb + tg + 4];
        a[3] = As[(mr + g + 8) * S + kb + tg + 4];
#pragma unroll
        for (int n = 0; n < 4; ++n) {
            int col = n * 8 + g;
            uint32_t bl[2], br[2];
            bl[0] = Bls[col * S + kb + tg];
            bl[1] = Bls[col * S + kb + tg + 4];
            br[0] = Brs[col * S + kb + tg];
            br[1] = Brs[col * S + kb + tg + 4];
            mma_bf16(accl[n], a, bl);
            mma_bf16(accr[n], a, br);
        }
    }

    const int r0 = m0 + mr + g;
    const int r1 = r0 + 8;
#pragma unroll
    for (int n = 0; n < 4; ++n) {
        int col = n * 8 + 2 * tg;
        if (r0 < N_NODES) {
            *(uint32_t*)((char*)Ylb + (size_t)r0 * 64 + col * 2) = pack_bf16(accl[n][0], accl[n][1]);
            *(float2*)(Yr + (size_t)r0 * 32 + col) = make_float2(accr[n][0], accr[n][1]);
        }
        if (r1 < N_NODES) {
            *(uint32_t*)((char*)Ylb + (size_t)r1 * 64 + col * 2) = pack_bf16(accl[n][2], accl[n][3]);
            *(float2*)(Yr + (size_t)r1 * 32 + col) = make_float2(accr[n][2], accr[n][3]);
        }
    }
}

// ---------------- aggregation: fp8 gather (2 edges/warp), half2 accumulation ----------------
__global__ void agg_relu_kernel(const uint8_t* __restrict__ ylq, const __nv_bfloat16* __restrict__ yrb,
                                const float* __restrict__ bl, __nv_bfloat16* __restrict__ hb) {
    int node = blockIdx.x * (blockDim.x >> 5) + (threadIdx.x >> 5);
    if (node >= N_NODES) return;
    int lane = threadIdx.x & 31;
    int g2 = lane >> 4;        // which edge of the pair
    int p  = lane & 15;        // feature slice: features [8p, 8p+8), 8 bytes fp8
    int beg = g_rowptr[node], end = g_rowptr[node + 1];
    uint32_t h0a = 0, h1a = 0, h2a = 0, h3a = 0;   // half2 accumulators (zero = 0.0h pair)
    int j = beg;
    for (; j + 8 <= end; j += 8) {
        uint2 u[4];
#pragma unroll
        for (int q = 0; q < 4; ++q) {
            int s = __ldg(&g_srcs[j + 2 * q + g2]);
            u[q] = *(const uint2*)(ylq + (size_t)s * 128 + p * 8);
        }
#pragma unroll
        for (int q = 0; q < 4; ++q) {
            h0a = hadd2(h0a, fp8x2_to_h2(u[q].x & 0xFFFFu));
            h1a = hadd2(h1a, fp8x2_to_h2(u[q].x >> 16));
            h2a = hadd2(h2a, fp8x2_to_h2(u[q].y & 0xFFFFu));
            h3a = hadd2(h3a, fp8x2_to_h2(u[q].y >> 16));
        }
    }
    for (; j + 2 <= end; j += 2) {
        int s = __ldg(&g_srcs[j + g2]);
        uint2 u = *(const uint2*)(ylq + (size_t)s * 128 + p * 8);
        h0a = hadd2(h0a, fp8x2_to_h2(u.x & 0xFFFFu));
        h1a = hadd2(h1a, fp8x2_to_h2(u.x >> 16));
        h2a = hadd2(h2a, fp8x2_to_h2(u.y & 0xFFFFu));
        h3a = hadd2(h3a, fp8x2_to_h2(u.y >> 16));
    }
    if (j < end && g2 == 0) {
        int s = __ldg(&g_srcs[j]);
        uint2 u = *(const uint2*)(ylq + (size_t)s * 128 + p * 8);
        h0a = hadd2(h0a, fp8x2_to_h2(u.x & 0xFFFFu));
        h1a = hadd2(h1a, fp8x2_to_h2(u.x >> 16));
        h2a = hadd2(h2a, fp8x2_to_h2(u.y & 0xFFFFu));
        h3a = hadd2(h3a, fp8x2_to_h2(u.y >> 16));
    }
    // merge the two half-warps
    h0a = hadd2(h0a, __shfl_xor_sync(0xFFFFFFFFu, h0a, 16));
    h1a = hadd2(h1a, __shfl_xor_sync(0xFFFFFFFFu, h1a, 16));
    h2a = hadd2(h2a, __shfl_xor_sync(0xFFFFFFFFu, h2a, 16));
    h3a = hadd2(h3a, __shfl_xor_sync(0xFFFFFFFFu, h3a, 16));

    if (g2 == 0) {
        float2 a01 = h2f2(h0a), a23 = h2f2(h1a), a45 = h2f2(h2a), a67 = h2f2(h3a);
        float id = g_invdeg[node];
        uint4 ur = *(const uint4*)((const char*)yrb + (size_t)node * 256 + p * 16);
        float2 r01 = __bfloat1622float2(*(__nv_bfloat162*)&ur.x);
        float2 r23 = __bfloat1622float2(*(__nv_bfloat162*)&ur.y);
        float2 r45 = __bfloat1622float2(*(__nv_bfloat162*)&ur.z);
        float2 r67 = __bfloat1622float2(*(__nv_bfloat162*)&ur.w);
        float4 b0 = ((const float4*)bl)[2 * p];
        float4 b1 = ((const float4*)bl)[2 * p + 1];
        float o0 = fmaxf(fmaf(a01.x, id, b0.x) + r01.x, 0.f);
        float o1 = fmaxf(fmaf(a01.y, id, b0.y) + r01.y, 0.f);
        float o2 = fmaxf(fmaf(a23.x, id, b0.z) + r23.x, 0.f);
        float o3 = fmaxf(fmaf(a23.y, id, b0.w) + r23.y, 0.f);
        float o4 = fmaxf(fmaf(a45.x, id, b1.x) + r45.x, 0.f);
        float o5 = fmaxf(fmaf(a45.y, id, b1.y) + r45.y, 0.f);
        float o6 = fmaxf(fmaf(a67.x, id, b1.z) + r67.x, 0.f);
        float o7 = fmaxf(fmaf(a67.y, id, b1.w) + r67.y, 0.f);
        uint4 ov = make_uint4(pack_bf16(o0, o1), pack_bf16(o2, o3),
                              pack_bf16(o4, o5), pack_bf16(o6, o7));
        *(uint4*)((char*)hb + (size_t)node * 256 + p * 16) = ov;
    }
}

// log_softmax layer: yl bf16 [N,32]; 2 edges per warp
__global__ void agg_lsm_kernel(const __nv_bfloat16* __restrict__ ylb, const float* __restrict__ yr,
                               const float* __restrict__ bl2, float* __restrict__ out) {
    int node = blockIdx.x * (blockDim.x >> 5) + (threadIdx.x >> 5);
    if (node >= N_NODES) return;
    int lane = threadIdx.x & 31;
    int g2 = lane >> 4;
    int p  = lane & 15;
    int beg = g_rowptr[node], end = g_rowptr[node + 1];
    float ax = 0.f, ay = 0.f;
    const uint32_t* yl32 = (const uint32_t*)ylb;
    int j = beg;
    for (; j + 4 <= end; j += 4) {
        int sA = __ldg(&g_srcs[j + g2]);
        int sB = __ldg(&g_srcs[j + 2 + g2]);
        uint32_t uA = __ldg(&yl32[(size_t)sA * 16 + p]);
        uint32_t uB = __ldg(&yl32[(size_t)sB * 16 + p]);
        float2 fA = __bfloat1622float2(*(__nv_bfloat162*)&uA);
        float2 fB = __bfloat1622float2(*(__nv_bfloat162*)&uB);
        ax += fA.x + fB.x; ay += fA.y + fB.y;
    }
    if (j + 2 <= end) {
        int s = __ldg(&g_srcs[j + g2]);
        uint32_t u = __ldg(&yl32[(size_t)s * 16 + p]);
        float2 f = __bfloat1622float2(*(__nv_bfloat162*)&u);
        ax += f.x; ay += f.y;
        j += 2;
    }
    if (j < end && g2 == 0) {
        int s = __ldg(&g_srcs[j]);
        uint32_t u = __ldg(&yl32[(size_t)s * 16 + p]);
        float2 f = __bfloat1622float2(*(__nv_bfloat162*)&u);
        ax += f.x; ay += f.y;
    }
    ax += __shfl_xor_sync(0xFFFFFFFFu, ax, 16);
    ay += __shfl_xor_sync(0xFFFFFFFFu, ay, 16);

    float id = g_invdeg[node];
    float2 b2 = ((const float2*)bl2)[p];
    float2 r2 = ((const float2*)yr)[(size_t)node * 16 + p];
    float v0 = fmaf(ax, id, b2.x) + r2.x;
    float v1 = fmaf(ay, id, b2.y) + r2.y;
    float m = fmaxf(v0, v1);
#pragma unroll
    for (int o = 1; o < 16; o <<= 1) m = fmaxf(m, __shfl_xor_sync(0xFFFFFFFFu, m, o));
    float s = expf(v0 - m) + expf(v1 - m);
#pragma unroll
    for (int o = 1; o < 16; o <<= 1) s += __shfl_xor_sync(0xFFFFFFFFu, s, o);
    float ls = logf(s);
    if (g2 == 0)
        ((float2*)out)[(size_t)node * 16 + p] = make_float2(v0 - m - ls, v1 - m - ls);
}

// ---------------- host ----------------
extern "C" void kernel_launch(void* const* d_in, const int* in_sizes, int n_in,
                              void* d_out, int out_size) {
    const float* x   = (const float*)d_in[0];
    const void*  ei  = d_in[1];
    const float* Wl0 = (const float*)d_in[2];
    const float* bl0 = (const float*)d_in[3];
    const float* Wr0 = (const float*)d_in[4];
    const float* Wl1 = (const float*)d_in[5];
    const float* bl1 = (const float*)d_in[6];
    const float* Wr1 = (const float*)d_in[7];
    const float* Wl2 = (const float*)d_in[8];
    const float* bl2 = (const float*)d_in[9];
    const float* Wr2 = (const float*)d_in[10];
    float* out = (float*)d_out;

    float *yl, *yr, *h0;
    uint32_t *wp128, *wp32;
    cudaGetSymbolAddress((void**)&yl, g_yl);
    cudaGetSymbolAddress((void**)&yr, g_yr);
    cudaGetSymbolAddress((void**)&h0, g_h0);
    cudaGetSymbolAddress((void**)&wp128, g_wp128);
    cudaGetSymbolAddress((void**)&wp32, g_wp32);
    uint8_t*       ylq = (uint8_t*)yl;          // fp8 [N,128] (L0/L1)
    __nv_bfloat16* ylb = (__nv_bfloat16*)yl;    // bf16 [N,32] (L2)
    __nv_bfloat16* yrb = (__nv_bfloat16*)yr;    // bf16 [N,128] (L0/L1)
    __nv_bfloat16* h0b = (__nv_bfloat16*)h0;

    static cudaStream_t s2 = nullptr;
    static cudaEvent_t ev_fork = nullptr, ev_join = nullptr;
    if (!s2) {
        cudaStreamCreateWithFlags(&s2, cudaStreamNonBlocking);
        cudaEventCreateWithFlags(&ev_fork, cudaEventDisableTiming);
        cudaEventCreateWithFlags(&ev_join, cudaEventDisableTiming);
    }

    const int SMEM128 = (2 * 64 * 68 + 2 * 128 * 68) * 4;
    const int SMEM32  = (128 * 68 + 2 * 32 * 68) * 4;
    cudaFuncSetAttribute(gemm128_dual_kernel<float>, cudaFuncAttributeMaxDynamicSharedMemorySize, SMEM128);
    cudaFuncSetAttribute(gemm128_dual_kernel<__nv_bfloat16>, cudaFuncAttributeMaxDynamicSharedMemorySize, SMEM128);
    cudaFuncSetAttribute(gemm32_dual_kernel, cudaFuncAttributeMaxDynamicSharedMemorySize, SMEM32);

    const int T = 256;
    const int NB = (N_NODES + T - 1) / T;
    const int EB = (N_EDGES + T - 1) / T;
    const int SCB = (N_NODES + SCAN_B - 1) / SCAN_B;
    const int AGG_B = (N_NODES + 7) / 8;
    const int GT32 = (N_NODES + 127) / 128;

    // front: CSR on s2 overlapped with pack + layer-0 GEMM on main (gemm = submission #4)
    cudaEventRecord(ev_fork, 0);
    cudaStreamWaitEvent(s2, ev_fork, 0);

    init_kernel<<<NB, T, 0, s2>>>((const int*)ei);                               // #1
    pack_w_kernel<<<144, 256>>>(Wl0, Wr0, Wl1, Wr1, Wl2, Wr2);                   // #2 (main)
    hist_kernel<<<EB, T, 0, s2>>>(ei);                                           // #3
    gemm128_dual_kernel<float><<<GEMM_GRID, 256, SMEM128>>>(x, wp128, wp128 + 8192, ylq, yrb);  // #4 (main)
    scan_block_kernel<<<SCB, SCAN_B, 0, s2>>>();                                 // #5
    scan_bsum_kernel<<<1, 128, 0, s2>>>(SCB);                                    // #6
    finalize_csr_kernel<<<NB, T, 0, s2>>>();                                     // #7
    fill_kernel<<<EB, T, 0, s2>>>(ei);                                           // #8
    cudaEventRecord(ev_join, s2);
    cudaStreamWaitEvent(0, ev_join, 0);

    // ---- Layer 0 aggregation ----
    agg_relu_kernel<<<AGG_B, T>>>(ylq, yrb, bl0, h0b);
    // ---- Layer 1 ----
    gemm128_dual_kernel<__nv_bfloat16><<<GEMM_GRID, 256, SMEM128>>>(h0b, wp128 + 2 * 8192, wp128 + 3 * 8192, ylq, yrb);
    agg_relu_kernel<<<AGG_B, T>>>(ylq, yrb, bl1, h0b);
    // ---- Layer 2 ----
    gemm32_dual_kernel<<<GT32, T, SMEM32>>>(h0b, wp32, wp32 + 2048, ylb, yr);
    agg_lsm_kernel<<<AGG_B, T>>>(ylb, yr, bl2, out);
}

// round 15
// speedup vs baseline: 1.1491x; 1.0241x over previous
#include <cuda_runtime.h>
#include <cuda_bf16.h>
#include <cuda_fp16.h>
#include <math.h>
#include <stdint.h>

#define N_NODES 100000
#define N_EDGES 1600000
#define D_HID 128
#define D_OUT 32
#define SCAN_B 1024
#define TILES128 ((N_NODES + 63) / 64)   // 1563
#define GEMM_GRID 296

// ---------------- scratch ----------------
__device__ float g_yl[(size_t)N_NODES * D_HID];   // L0/L1: fp8 [N,128]; L2: bf16 [N,32]
__device__ float g_yr[(size_t)N_NODES * D_HID];   // L0/L1: bf16 [N,128]; L2: fp32 [N,32]
__device__ float g_h0[(size_t)N_NODES * D_HID];   // bf16 [N,128] activations
__device__ float g_invdeg[N_NODES];
__device__ int   g_cnt[N_NODES];
__device__ int   g_rowptr[N_NODES + 1];
__device__ int   g_fill[N_NODES];
__device__ int   g_srcs[N_EDGES];
__device__ int   g_bsum[(N_NODES + SCAN_B - 1) / SCAN_B];
__device__ int   g_boff[(N_NODES + SCAN_B - 1) / SCAN_B];
__device__ int   g_idx64;
__device__ uint32_t g_wp128[4][128 * 64];
__device__ uint32_t g_wp32[2][32 * 64];

// ---------------- helpers ----------------
__device__ __forceinline__ void mma_bf16(float c[4], const uint32_t a[4], const uint32_t b[2]) {
    asm volatile(
        "mma.sync.aligned.m16n8k16.row.col.f32.bf16.bf16.f32 "
        "{%0,%1,%2,%3}, {%4,%5,%6,%7}, {%8,%9}, {%0,%1,%2,%3};"
        : "+f"(c[0]), "+f"(c[1]), "+f"(c[2]), "+f"(c[3])
        : "r"(a[0]), "r"(a[1]), "r"(a[2]), "r"(a[3]), "r"(b[0]), "r"(b[1]));
}
__device__ __forceinline__ uint32_t pack_bf16(float a, float b) {
    __nv_bfloat162 p = __floats2bfloat162_rn(a, b);
    return *(uint32_t*)&p;
}
__device__ __forceinline__ uint16_t pack_e4m3(float a, float b) {
    uint16_t r;
    asm("cvt.rn.satfinite.e4m3x2.f32 %0, %1, %2;" : "=h"(r) : "f"(b), "f"(a));
    return r;
}
__device__ __forceinline__ uint32_t fp8x2_to_h2(uint32_t v) {
    uint32_t r;
    asm("cvt.rn.f16x2.e4m3x2 %0, %1;" : "=r"(r) : "h"((uint16_t)v));
    return r;
}
__device__ __forceinline__ uint32_t hadd2(uint32_t a, uint32_t b) {
    uint32_t r;
    asm("add.f16x2 %0, %1, %2;" : "=r"(r) : "r"(a), "r"(b));
    return r;
}
__device__ __forceinline__ float2 h2f2(uint32_t h) {
    __half2 v = *(__half2*)&h;
    return __half22float2(v);
}
__device__ __forceinline__ void ldsm_x4(uint32_t r[4], uint32_t addr) {
    asm volatile("ldmatrix.sync.aligned.m8n8.x4.shared.b16 {%0,%1,%2,%3}, [%4];"
                 : "=r"(r[0]), "=r"(r[1]), "=r"(r[2]), "=r"(r[3]) : "r"(addr));
}
__device__ __forceinline__ void ldsm_x2(uint32_t r[2], uint32_t addr) {
    asm volatile("ldmatrix.sync.aligned.m8n8.x2.shared.b16 {%0,%1}, [%2];"
                 : "=r"(r[0]), "=r"(r[1]) : "r"(addr));
}
__device__ __forceinline__ uint32_t smem_u32(const void* p) {
    return (uint32_t)__cvta_generic_to_shared(p);
}

// ---------------- edge index access ----------------
__device__ __forceinline__ int edge_src(const void* __restrict__ ei, int e) {
    return g_idx64 ? (int)((const long long*)ei)[e] : ((const int*)ei)[e];
}
__device__ __forceinline__ int edge_dst(const void* __restrict__ ei, int e) {
    return g_idx64 ? (int)((const long long*)ei)[N_EDGES + e] : ((const int*)ei)[N_EDGES + e];
}

// ---------------- weight pre-pack ----------------
__global__ void pack_w_kernel(const float* __restrict__ Wl0, const float* __restrict__ Wr0,
                              const float* __restrict__ Wl1, const float* __restrict__ Wr1,
                              const float* __restrict__ Wl2, const float* __restrict__ Wr2) {
    int idx = blockIdx.x * blockDim.x + threadIdx.x;
    if (idx < 4 * 8192) {
        int mat = idx >> 13, r = idx & 8191;
        int kp = r >> 7, n = r & 127;
        const float* W = (mat == 0) ? Wl0 : (mat == 1) ? Wr0 : (mat == 2) ? Wl1 : Wr1;
        g_wp128[mat][n * 64 + kp] = pack_bf16(W[(2 * kp) * 128 + n], W[(2 * kp + 1) * 128 + n]);
    } else {
        int r2 = idx - 32768;
        if (r2 < 2 * 2048) {
            int mat = r2 >> 11, r = r2 & 2047;
            int kp = r >> 5, n = r & 31;
            const float* W = mat ? Wr2 : Wl2;
            g_wp32[mat][n * 64 + kp] = pack_bf16(W[(2 * kp) * 32 + n], W[(2 * kp + 1) * 32 + n]);
        }
    }
}

// ---------------- CSR build ----------------
__global__ void init_kernel(const int* __restrict__ ei32) {
    int i = blockIdx.x * blockDim.x + threadIdx.x;
    if (i == 0) {
        int all0 = 1;
#pragma unroll
        for (int k = 1; k < 64; k += 2) all0 &= (ei32[k] == 0);
        g_idx64 = all0;
    }
    if (i < N_NODES) g_cnt[i] = 0;
}
__global__ void hist_kernel(const void* __restrict__ ei) {
    int e = blockIdx.x * blockDim.x + threadIdx.x;
    if (e < N_EDGES) atomicAdd(&g_cnt[edge_dst(ei, e)], 1);
}
__global__ void scan_block_kernel() {
    __shared__ int sb[2][SCAN_B];
    int tid = threadIdx.x;
    int i = blockIdx.x * SCAN_B + tid;
    int v = (i < N_NODES) ? g_cnt[i] : 0;
    sb[0][tid] = v;
    int cur = 0;
#pragma unroll
    for (int d = 1; d < SCAN_B; d <<= 1) {
        __syncthreads();
        int nv = sb[cur][tid] + (tid >= d ? sb[cur][tid - d] : 0);
        sb[cur ^ 1][tid] = nv;
        cur ^= 1;
    }
    __syncthreads();
    if (i < N_NODES) g_rowptr[i + 1] = sb[cur][tid];
    if (tid == SCAN_B - 1) g_bsum[blockIdx.x] = sb[cur][tid];
    if (i == 0) g_rowptr[0] = 0;
}
__global__ void scan_bsum_kernel(int nblocks) {
    __shared__ int sm2[2][128];
    int tid = threadIdx.x;
    int v = (tid < nblocks) ? g_bsum[tid] : 0;
    sm2[0][tid] = v;
    int cur = 0;
#pragma unroll
    for (int d = 1; d < 128; d <<= 1) {
        __syncthreads();
        int nv = sm2[cur][tid] + (tid >= d ? sm2[cur][tid - d] : 0);
        sm2[cur ^ 1][tid] = nv;
        cur ^= 1;
    }
    __syncthreads();
    if (tid < nblocks) g_boff[tid] = sm2[cur][tid] - v;
}
__global__ void finalize_csr_kernel() {
    int i = blockIdx.x * blockDim.x + threadIdx.x;
    if (i >= N_NODES) return;
    int off = g_boff[i / SCAN_B];
    int end = g_rowptr[i + 1] + off;
    g_rowptr[i + 1] = end;
    int c = g_cnt[i];
    g_fill[i] = end - c;
    g_invdeg[i] = 1.0f / fmaxf((float)c, 1.0f);
}
__global__ void fill_kernel(const void* __restrict__ ei) {
    int e = blockIdx.x * blockDim.x + threadIdx.x;
    if (e >= N_EDGES) return;
    int d = edge_dst(ei, e);
    int pos = atomicAdd(&g_fill[d], 1);
    g_srcs[pos] = edge_src(ei, e);
}

// ---------------- persistent dual GEMM, DO=128: Yl fp8 (smem-staged), Yr bf16 ----------------
template <typename TIN>
__launch_bounds__(256, 2)
__global__ void gemm128_dual_kernel(const TIN* __restrict__ X,
                                    const uint32_t* __restrict__ wpl, const uint32_t* __restrict__ wpr,
                                    uint8_t* __restrict__ Ylq, __nv_bfloat16* __restrict__ Yrb) {
    constexpr int S = 68;
    constexpr int ABUF = 64 * S;
    extern __shared__ uint32_t sm[];
    uint32_t* As0 = sm;
    uint32_t* As1 = sm + ABUF;
    uint32_t* Bls = sm + 2 * ABUF;
    uint32_t* Brs = Bls + 128 * S;
    uint8_t*  Stg = (uint8_t*)(Brs + 128 * S);   // 64 rows x 128 B fp8 staging (8KB)

    const int t = threadIdx.x;
    const int w = t >> 5;
    const int lane = t & 31;
    const int g = lane >> 2, tg = lane & 3;

#pragma unroll
    for (int it = 0; it < 8; ++it) {
        int i4 = t + it * 256;
        int n = i4 >> 4, kp4 = (i4 & 15) * 4;
        *(uint4*)(Bls + n * S + kp4) = ((const uint4*)wpl)[i4];
        *(uint4*)(Brs + n * S + kp4) = ((const uint4*)wpr)[i4];
    }

    auto fill_A = [&](uint32_t* As, int m0) {
        if constexpr (sizeof(TIN) == 4) {
#pragma unroll
            for (int it = 0; it < 8; ++it) {
                int idx = t + it * 256;
                int row = idx >> 5, c4 = idx & 31;
                int gr  = m0 + row;
                float4 v = make_float4(0.f, 0.f, 0.f, 0.f);
                if (gr < N_NODES) v = *(const float4*)((const float*)X + (size_t)gr * 128 + c4 * 4);
                uint32_t* p = As + row * S + c4 * 2;
                p[0] = pack_bf16(v.x, v.y);
                p[1] = pack_bf16(v.z, v.w);
            }
        } else {
#pragma unroll
            for (int it = 0; it < 4; ++it) {
                int idx = t + it * 256;
                int row = idx >> 4, q = idx & 15;
                int gr  = m0 + row;
                uint4 v = make_uint4(0, 0, 0, 0);
                if (gr < N_NODES) v = ((const uint4*)X)[(size_t)gr * 16 + q];
                *(uint4*)(As + row * S + q * 4) = v;
            }
        }
    };

    if ((int)blockIdx.x < TILES128) fill_A(As0, blockIdx.x * 64);
    __syncthreads();

    const int mgrp = w & 1;
    const int ngrp = (w >> 1) & 1;
    const int isR  = w >> 2;
    const int mr = mgrp * 32;
    const int nb = ngrp * 64;

    const uint32_t a_lane_off = ((mr + (lane & 7) + ((lane >> 3) & 1) * 8) * S + ((lane >> 4) << 2)) * 4;
    const int l15 = lane & 15;
    const uint32_t b_lane = ((nb + (l15 & 7)) * S + ((l15 >> 3) << 2)) * 4;
    const uint32_t bs_base = smem_u32(isR ? Brs : Bls) + b_lane;
    const uint32_t as0 = smem_u32(As0);
    const uint32_t as1 = smem_u32(As1);

    int buf = 0;
    for (int tile = blockIdx.x; tile < TILES128; tile += GEMM_GRID, buf ^= 1) {
        const int m0 = tile * 64;
        const uint32_t as_base = (buf ? as1 : as0) + a_lane_off;

        float acc[2][8][4];
#pragma unroll
        for (int m = 0; m < 2; ++m)
#pragma unroll
            for (int n = 0; n < 8; ++n)
#pragma unroll
                for (int q = 0; q < 4; ++q) acc[m][n][q] = 0.f;

#pragma unroll
        for (int kt = 0; kt < 8; ++kt) {
            const uint32_t kb = kt * 32;
            uint32_t a0[4], a1[4];
            ldsm_x4(a0, as_base + kb);
            ldsm_x4(a1, as_base + 16 * S * 4 + kb);
#pragma unroll
            for (int n = 0; n < 8; ++n) {
                uint32_t b[2];
                ldsm_x2(b, bs_base + n * (8 * S * 4) + kb);
                mma_bf16(acc[0][n], a0, b);
                mma_bf16(acc[1][n], a1, b);
            }
        }

        int nt = tile + GEMM_GRID;
        if (nt < TILES128) fill_A(buf ? As0 : As1, nt * 64);

        if (!isR) {
            // ---- Yl (fp8): pack to smem staging, then coalesced STG.128 ----
#pragma unroll
            for (int m = 0; m < 2; ++m) {
                const int lr0 = mr + m * 16 + g;
#pragma unroll
                for (int n = 0; n < 8; ++n) {
                    int col = nb + n * 8 + 2 * tg;
                    *(uint16_t*)(Stg + lr0 * 128 + col)       = pack_e4m3(acc[m][n][0], acc[m][n][1]);
                    *(uint16_t*)(Stg + (lr0 + 8) * 128 + col) = pack_e4m3(acc[m][n][2], acc[m][n][3]);
                }
            }
            asm volatile("bar.sync 1, 128;" ::: "memory");
#pragma unroll
            for (int it = 0; it < 4; ++it) {
                int i4 = t + it * 128;          // 512 uint4 slots (threads 0..127)
                int row = i4 >> 3, q = i4 & 7;
                int gr = m0 + row;
                if (gr < N_NODES)
                    *(uint4*)(Ylq + (size_t)gr * 128 + q * 16) = *(const uint4*)(Stg + row * 128 + q * 16);
            }
        } else {
            // ---- Yr (bf16): direct STG.32 as before ----
#pragma unroll
            for (int m = 0; m < 2; ++m) {
                const int r0 = m0 + mr + m * 16 + g;
                const int r1 = r0 + 8;
#pragma unroll
                for (int n = 0; n < 8; ++n) {
                    int col = nb + n * 8 + 2 * tg;
                    if (r0 < N_NODES)
                        *(uint32_t*)((char*)Yrb + (size_t)r0 * 256 + col * 2) = pack_bf16(acc[m][n][0], acc[m][n][1]);
                    if (r1 < N_NODES)
                        *(uint32_t*)((char*)Yrb + (size_t)r1 * 256 + col * 2) = pack_bf16(acc[m][n][2], acc[m][n][3]);
                }
            }
        }
        __syncthreads();
    }
}

// ---------------- dual GEMM, DO=32: Yl bf16, Yr fp32 ----------------
__launch_bounds__(256, 2)
__global__ void gemm32_dual_kernel(const __nv_bfloat16* __restrict__ X,
                                   const uint32_t* __restrict__ wpl, const uint32_t* __restrict__ wpr,
                                   __nv_bfloat16* __restrict__ Ylb, float* __restrict__ Yr) {
    constexpr int S = 68;
    extern __shared__ uint32_t sm[];
    uint32_t* As  = sm;
    uint32_t* Bls = sm + 128 * S;
    uint32_t* Brs = Bls + 32 * S;

    const int t = threadIdx.x;
    const int w = t >> 5;
    const int lane = t & 31;
    const int g = lane >> 2, tg = lane & 3;
    const int m0 = blockIdx.x * 128;

#pragma unroll
    for (int it = 0; it < 8; ++it) {
        int idx = t + it * 256;
        int row = idx >> 4, q = idx & 15;
        int gr  = m0 + row;
        uint4 v = make_uint4(0, 0, 0, 0);
        if (gr < N_NODES) v = ((const uint4*)X)[(size_t)gr * 16 + q];
        *(uint4*)(As + row * S + q * 4) = v;
    }
#pragma unroll
    for (int it = 0; it < 2; ++it) {
        int i4 = t + it * 256;
        int n = i4 >> 4, kp4 = (i4 & 15) * 4;
        *(uint4*)(Bls + n * S + kp4) = ((const uint4*)wpl)[i4];
        *(uint4*)(Brs + n * S + kp4) = ((const uint4*)wpr)[i4];
    }
    __syncthreads();

    const int mr = w * 16;
    float accl[4][4], accr[4][4];
#pragma unroll
    for (int n = 0; n < 4; ++n)
#pragma unroll
        for (int q = 0; q < 4; ++q) { accl[n][q] = 0.f; accr[n][q] = 0.f; }

#pragma unroll
    for (int kt = 0; kt < 8; ++kt) {
        const int kb = kt * 8;
        uint32_t a[4];
        a[0] = As[(mr + g)     * S + kb + tg];
        a[1] = As[(mr + g + 8) * S + kb + tg];
        a[2] = As[(mr + g)     * S + kb + tg + 4];
        a[3] = As[(mr + g + 8) * S + kb + tg + 4];
#pragma unroll
        for (int n = 0; n < 4; ++n) {
            int col = n * 8 + g;
            uint32_t bl[2], br[2];
            bl[0] = Bls[col * S + kb + tg];
            bl[1] = Bls[col * S + kb + tg + 4];
            br[0] = Brs[col * S + kb + tg];
            br[1] = Brs[col * S + kb + tg + 4];
            mma_bf16(accl[n], a, bl);
            mma_bf16(accr[n], a, br);
        }
    }

    const int r0 = m0 + mr + g;
    const int r1 = r0 + 8;
#pragma unroll
    for (int n = 0; n < 4; ++n) {
        int col = n * 8 + 2 * tg;
        if (r0 < N_NODES) {
            *(uint32_t*)((char*)Ylb + (size_t)r0 * 64 + col * 2) = pack_bf16(accl[n][0], accl[n][1]);
            *(float2*)(Yr + (size_t)r0 * 32 + col) = make_float2(accr[n][0], accr[n][1]);
        }
        if (r1 < N_NODES) {
            *(uint32_t*)((char*)Ylb + (size_t)r1 * 64 + col * 2) = pack_bf16(accl[n][2], accl[n][3]);
            *(float2*)(Yr + (size_t)r1 * 32 + col) = make_float2(accr[n][2], accr[n][3]);
        }
    }
}

// ---------------- aggregation: fp8 gather (2 edges/warp), half2 accumulation ----------------
__global__ void agg_relu_kernel(const uint8_t* __restrict__ ylq, const __nv_bfloat16* __restrict__ yrb,
                                const float* __restrict__ bl, __nv_bfloat16* __restrict__ hb) {
    int node = blockIdx.x * (blockDim.x >> 5) + (threadIdx.x >> 5);
    if (node >= N_NODES) return;
    int lane = threadIdx.x & 31;
    int g2 = lane >> 4;
    int p  = lane & 15;
    int beg = g_rowptr[node], end = g_rowptr[node + 1];
    uint32_t h0a = 0, h1a = 0, h2a = 0, h3a = 0;
    int j = beg;
    for (; j + 8 <= end; j += 8) {
        uint2 u[4];
#pragma unroll
        for (int q = 0; q < 4; ++q) {
            int s = __ldg(&g_srcs[j + 2 * q + g2]);
            u[q] = *(const uint2*)(ylq + (size_t)s * 128 + p * 8);
        }
#pragma unroll
        for (int q = 0; q < 4; ++q) {
            h0a = hadd2(h0a, fp8x2_to_h2(u[q].x & 0xFFFFu));
            h1a = hadd2(h1a, fp8x2_to_h2(u[q].x >> 16));
            h2a = hadd2(h2a, fp8x2_to_h2(u[q].y & 0xFFFFu));
            h3a = hadd2(h3a, fp8x2_to_h2(u[q].y >> 16));
        }
    }
    for (; j + 2 <= end; j += 2) {
        int s = __ldg(&g_srcs[j + g2]);
        uint2 u = *(const uint2*)(ylq + (size_t)s * 128 + p * 8);
        h0a = hadd2(h0a, fp8x2_to_h2(u.x & 0xFFFFu));
        h1a = hadd2(h1a, fp8x2_to_h2(u.x >> 16));
        h2a = hadd2(h2a, fp8x2_to_h2(u.y & 0xFFFFu));
        h3a = hadd2(h3a, fp8x2_to_h2(u.y >> 16));
    }
    if (j < end && g2 == 0) {
        int s = __ldg(&g_srcs[j]);
        uint2 u = *(const uint2*)(ylq + (size_t)s * 128 + p * 8);
        h0a = hadd2(h0a, fp8x2_to_h2(u.x & 0xFFFFu));
        h1a = hadd2(h1a, fp8x2_to_h2(u.x >> 16));
        h2a = hadd2(h2a, fp8x2_to_h2(u.y & 0xFFFFu));
        h3a = hadd2(h3a, fp8x2_to_h2(u.y >> 16));
    }
    h0a = hadd2(h0a, __shfl_xor_sync(0xFFFFFFFFu, h0a, 16));
    h1a = hadd2(h1a, __shfl_xor_sync(0xFFFFFFFFu, h1a, 16));
    h2a = hadd2(h2a, __shfl_xor_sync(0xFFFFFFFFu, h2a, 16));
    h3a = hadd2(h3a, __shfl_xor_sync(0xFFFFFFFFu, h3a, 16));

    if (g2 == 0) {
        float2 a01 = h2f2(h0a), a23 = h2f2(h1a), a45 = h2f2(h2a), a67 = h2f2(h3a);
        float id = g_invdeg[node];
        uint4 ur = *(const uint4*)((const char*)yrb + (size_t)node * 256 + p * 16);
        float2 r01 = __bfloat1622float2(*(__nv_bfloat162*)&ur.x);
        float2 r23 = __bfloat1622float2(*(__nv_bfloat162*)&ur.y);
        float2 r45 = __bfloat1622float2(*(__nv_bfloat162*)&ur.z);
        float2 r67 = __bfloat1622float2(*(__nv_bfloat162*)&ur.w);
        float4 b0 = ((const float4*)bl)[2 * p];
        float4 b1 = ((const float4*)bl)[2 * p + 1];
        float o0 = fmaxf(fmaf(a01.x, id, b0.x) + r01.x, 0.f);
        float o1 = fmaxf(fmaf(a01.y, id, b0.y) + r01.y, 0.f);
        float o2 = fmaxf(fmaf(a23.x, id, b0.z) + r23.x, 0.f);
        float o3 = fmaxf(fmaf(a23.y, id, b0.w) + r23.y, 0.f);
        float o4 = fmaxf(fmaf(a45.x, id, b1.x) + r45.x, 0.f);
        float o5 = fmaxf(fmaf(a45.y, id, b1.y) + r45.y, 0.f);
        float o6 = fmaxf(fmaf(a67.x, id, b1.z) + r67.x, 0.f);
        float o7 = fmaxf(fmaf(a67.y, id, b1.w) + r67.y, 0.f);
        uint4 ov = make_uint4(pack_bf16(o0, o1), pack_bf16(o2, o3),
                              pack_bf16(o4, o5), pack_bf16(o6, o7));
        *(uint4*)((char*)hb + (size_t)node * 256 + p * 16) = ov;
    }
}

// log_softmax layer: yl bf16 [N,32]; 2 edges per warp
__global__ void agg_lsm_kernel(const __nv_bfloat16* __restrict__ ylb, const float* __restrict__ yr,
                               const float* __restrict__ bl2, float* __restrict__ out) {
    int node = blockIdx.x * (blockDim.x >> 5) + (threadIdx.x >> 5);
    if (node >= N_NODES) return;
    int lane = threadIdx.x & 31;
    int g2 = lane >> 4;
    int p  = lane & 15;
    int beg = g_rowptr[node], end = g_rowptr[node + 1];
    float ax = 0.f, ay = 0.f;
    const uint32_t* yl32 = (const uint32_t*)ylb;
    int j = beg;
    for (; j + 4 <= end; j += 4) {
        int sA = __ldg(&g_srcs[j + g2]);
        int sB = __ldg(&g_srcs[j + 2 + g2]);
        uint32_t uA = __ldg(&yl32[(size_t)sA * 16 + p]);
        uint32_t uB = __ldg(&yl32[(size_t)sB * 16 + p]);
        float2 fA = __bfloat1622float2(*(__nv_bfloat162*)&uA);
        float2 fB = __bfloat1622float2(*(__nv_bfloat162*)&uB);
        ax += fA.x + fB.x; ay += fA.y + fB.y;
    }
    if (j + 2 <= end) {
        int s = __ldg(&g_srcs[j + g2]);
        uint32_t u = __ldg(&yl32[(size_t)s * 16 + p]);
        float2 f = __bfloat1622float2(*(__nv_bfloat162*)&u);
        ax += f.x; ay += f.y;
        j += 2;
    }
    if (j < end && g2 == 0) {
        int s = __ldg(&g_srcs[j]);
        uint32_t u = __ldg(&yl32[(size_t)s * 16 + p]);
        float2 f = __bfloat1622float2(*(__nv_bfloat162*)&u);
        ax += f.x; ay += f.y;
    }
    ax += __shfl_xor_sync(0xFFFFFFFFu, ax, 16);
    ay += __shfl_xor_sync(0xFFFFFFFFu, ay, 16);

    float id = g_invdeg[node];
    float2 b2 = ((const float2*)bl2)[p];
    float2 r2 = ((const float2*)yr)[(size_t)node * 16 + p];
    float v0 = fmaf(ax, id, b2.x) + r2.x;
    float v1 = fmaf(ay, id, b2.y) + r2.y;
    float m = fmaxf(v0, v1);
#pragma unroll
    for (int o = 1; o < 16; o <<= 1) m = fmaxf(m, __shfl_xor_sync(0xFFFFFFFFu, m, o));
    float s = expf(v0 - m) + expf(v1 - m);
#pragma unroll
    for (int o = 1; o < 16; o <<= 1) s += __shfl_xor_sync(0xFFFFFFFFu, s, o);
    float ls = logf(s);
    if (g2 == 0)
        ((float2*)out)[(size_t)node * 16 + p] = make_float2(v0 - m - ls, v1 - m - ls);
}

// ---------------- host ----------------
extern "C" void kernel_launch(void* const* d_in, const int* in_sizes, int n_in,
                              void* d_out, int out_size) {
    const float* x   = (const float*)d_in[0];
    const void*  ei  = d_in[1];
    const float* Wl0 = (const float*)d_in[2];
    const float* bl0 = (const float*)d_in[3];
    const float* Wr0 = (const float*)d_in[4];
    const float* Wl1 = (const float*)d_in[5];
    const float* bl1 = (const float*)d_in[6];
    const float* Wr1 = (const float*)d_in[7];
    const float* Wl2 = (const float*)d_in[8];
    const float* bl2 = (const float*)d_in[9];
    const float* Wr2 = (const float*)d_in[10];
    float* out = (float*)d_out;

    float *yl, *yr, *h0;
    uint32_t *wp128, *wp32;
    cudaGetSymbolAddress((void**)&yl, g_yl);
    cudaGetSymbolAddress((void**)&yr, g_yr);
    cudaGetSymbolAddress((void**)&h0, g_h0);
    cudaGetSymbolAddress((void**)&wp128, g_wp128);
    cudaGetSymbolAddress((void**)&wp32, g_wp32);
    uint8_t*       ylq = (uint8_t*)yl;
    __nv_bfloat16* ylb = (__nv_bfloat16*)yl;
    __nv_bfloat16* yrb = (__nv_bfloat16*)yr;
    __nv_bfloat16* h0b = (__nv_bfloat16*)h0;

    static cudaStream_t s2 = nullptr;
    static cudaEvent_t ev_fork = nullptr, ev_join = nullptr;
    if (!s2) {
        cudaStreamCreateWithFlags(&s2, cudaStreamNonBlocking);
        cudaEventCreateWithFlags(&ev_fork, cudaEventDisableTiming);
        cudaEventCreateWithFlags(&ev_join, cudaEventDisableTiming);
    }

    const int SMEM128 = (2 * 64 * 68 + 2 * 128 * 68) * 4 + 64 * 128;  // +8KB staging = 112640
    const int SMEM32  = (128 * 68 + 2 * 32 * 68) * 4;
    cudaFuncSetAttribute(gemm128_dual_kernel<float>, cudaFuncAttributeMaxDynamicSharedMemorySize, SMEM128);
    cudaFuncSetAttribute(gemm128_dual_kernel<__nv_bfloat16>, cudaFuncAttributeMaxDynamicSharedMemorySize, SMEM128);
    cudaFuncSetAttribute(gemm32_dual_kernel, cudaFuncAttributeMaxDynamicSharedMemorySize, SMEM32);

    const int T = 256;
    const int NB = (N_NODES + T - 1) / T;
    const int EB = (N_EDGES + T - 1) / T;
    const int SCB = (N_NODES + SCAN_B - 1) / SCAN_B;
    const int AGG_B = (N_NODES + 7) / 8;
    const int GT32 = (N_NODES + 127) / 128;

    // front: CSR on s2 overlapped with pack + layer-0 GEMM on main (gemm = submission #4)
    cudaEventRecord(ev_fork, 0);
    cudaStreamWaitEvent(s2, ev_fork, 0);

    init_kernel<<<NB, T, 0, s2>>>((const int*)ei);                               // #1
    pack_w_kernel<<<144, 256>>>(Wl0, Wr0, Wl1, Wr1, Wl2, Wr2);                   // #2 (main)
    hist_kernel<<<EB, T, 0, s2>>>(ei);                                           // #3
    gemm128_dual_kernel<float><<<GEMM_GRID, 256, SMEM128>>>(x, wp128, wp128 + 8192, ylq, yrb);  // #4 (main)
    scan_block_kernel<<<SCB, SCAN_B, 0, s2>>>();                                 // #5
    scan_bsum_kernel<<<1, 128, 0, s2>>>(SCB);                                    // #6
    finalize_csr_kernel<<<NB, T, 0, s2>>>();                                     // #7
    fill_kernel<<<EB, T, 0, s2>>>(ei);                                           // #8
    cudaEventRecord(ev_join, s2);
    cudaStreamWaitEvent(0, ev_join, 0);

    // ---- Layer 0 aggregation ----
    agg_relu_kernel<<<AGG_B, T>>>(ylq, yrb, bl0, h0b);
    // ---- Layer 1 ----
    gemm128_dual_kernel<__nv_bfloat16><<<GEMM_GRID, 256, SMEM128>>>(h0b, wp128 + 2 * 8192, wp128 + 3 * 8192, ylq, yrb);
    agg_relu_kernel<<<AGG_B, T>>>(ylq, yrb, bl1, h0b);
    // ---- Layer 2 ----
    gemm32_dual_kernel<<<GT32, T, SMEM32>>>(h0b, wp32, wp32 + 2048, ylb, yr);
    agg_lsm_kernel<<<AGG_B, T>>>(ylb, yr, bl2, out);
}

// round 16
// speedup vs baseline: 1.1767x; 1.0240x over previous
#include <cuda_runtime.h>
#include <cuda_bf16.h>
#include <cuda_fp16.h>
#include <math.h>
#include <stdint.h>

#define N_NODES 100000
#define N_EDGES 1600000
#define D_HID 128
#define D_OUT 32
#define SCAN_B 1024
#define TILES128 ((N_NODES + 63) / 64)   // 1563
#define GEMM_GRID 296

// ---------------- scratch ----------------
__device__ float g_yl[(size_t)N_NODES * D_HID];   // L0/L1: fp8 [N,128]; L2: bf16 [N,32]
__device__ float g_yr[(size_t)N_NODES * D_HID];   // L0/L1: bf16 [N,128]; L2: fp32 [N,32]
__device__ float g_h0[(size_t)N_NODES * D_HID];   // bf16 [N,128] activations
__device__ float g_invdeg[N_NODES];
__device__ int   g_cnt[N_NODES];
__device__ int   g_rowptr[N_NODES + 1];
__device__ int   g_fill[N_NODES];
__device__ int   g_srcs[N_EDGES];
__device__ int   g_bsum[(N_NODES + SCAN_B - 1) / SCAN_B];
__device__ int   g_boff[(N_NODES + SCAN_B - 1) / SCAN_B];
__device__ int   g_idx64;
__device__ uint32_t g_wp128[4][128 * 64];
__device__ uint32_t g_wp32[2][32 * 64];

// ---------------- helpers ----------------
__device__ __forceinline__ void mma_bf16(float c[4], const uint32_t a[4], const uint32_t b[2]) {
    asm volatile(
        "mma.sync.aligned.m16n8k16.row.col.f32.bf16.bf16.f32 "
        "{%0,%1,%2,%3}, {%4,%5,%6,%7}, {%8,%9}, {%0,%1,%2,%3};"
        : "+f"(c[0]), "+f"(c[1]), "+f"(c[2]), "+f"(c[3])
        : "r"(a[0]), "r"(a[1]), "r"(a[2]), "r"(a[3]), "r"(b[0]), "r"(b[1]));
}
__device__ __forceinline__ uint32_t pack_bf16(float a, float b) {
    __nv_bfloat162 p = __floats2bfloat162_rn(a, b);
    return *(uint32_t*)&p;
}
__device__ __forceinline__ uint16_t pack_e4m3(float a, float b) {
    uint16_t r;
    asm("cvt.rn.satfinite.e4m3x2.f32 %0, %1, %2;" : "=h"(r) : "f"(b), "f"(a));
    return r;
}
__device__ __forceinline__ uint32_t fp8x2_to_h2(uint32_t v) {
    uint32_t r;
    asm("cvt.rn.f16x2.e4m3x2 %0, %1;" : "=r"(r) : "h"((uint16_t)v));
    return r;
}
__device__ __forceinline__ uint32_t hadd2(uint32_t a, uint32_t b) {
    uint32_t r;
    asm("add.f16x2 %0, %1, %2;" : "=r"(r) : "r"(a), "r"(b));
    return r;
}
__device__ __forceinline__ float2 h2f2(uint32_t h) {
    __half2 v = *(__half2*)&h;
    return __half22float2(v);
}
__device__ __forceinline__ void ldsm_x4(uint32_t r[4], uint32_t addr) {
    asm volatile("ldmatrix.sync.aligned.m8n8.x4.shared.b16 {%0,%1,%2,%3}, [%4];"
                 : "=r"(r[0]), "=r"(r[1]), "=r"(r[2]), "=r"(r[3]) : "r"(addr));
}
__device__ __forceinline__ uint32_t smem_u32(const void* p) {
    return (uint32_t)__cvta_generic_to_shared(p);
}

// ---------------- edge index access ----------------
__device__ __forceinline__ int edge_src(const void* __restrict__ ei, int e) {
    return g_idx64 ? (int)((const long long*)ei)[e] : ((const int*)ei)[e];
}
__device__ __forceinline__ int edge_dst(const void* __restrict__ ei, int e) {
    return g_idx64 ? (int)((const long long*)ei)[N_EDGES + e] : ((const int*)ei)[N_EDGES + e];
}

// ---------------- weight pre-pack ----------------
__global__ void pack_w_kernel(const float* __restrict__ Wl0, const float* __restrict__ Wr0,
                              const float* __restrict__ Wl1, const float* __restrict__ Wr1,
                              const float* __restrict__ Wl2, const float* __restrict__ Wr2) {
    int idx = blockIdx.x * blockDim.x + threadIdx.x;
    if (idx < 4 * 8192) {
        int mat = idx >> 13, r = idx & 8191;
        int kp = r >> 7, n = r & 127;
        const float* W = (mat == 0) ? Wl0 : (mat == 1) ? Wr0 : (mat == 2) ? Wl1 : Wr1;
        g_wp128[mat][n * 64 + kp] = pack_bf16(W[(2 * kp) * 128 + n], W[(2 * kp + 1) * 128 + n]);
    } else {
        int r2 = idx - 32768;
        if (r2 < 2 * 2048) {
            int mat = r2 >> 11, r = r2 & 2047;
            int kp = r >> 5, n = r & 31;
            const float* W = mat ? Wr2 : Wl2;
            g_wp32[mat][n * 64 + kp] = pack_bf16(W[(2 * kp) * 32 + n], W[(2 * kp + 1) * 32 + n]);
        }
    }
}

// ---------------- CSR build ----------------
__global__ void init_kernel(const int* __restrict__ ei32) {
    int i = blockIdx.x * blockDim.x + threadIdx.x;
    if (i == 0) {
        int all0 = 1;
#pragma unroll
        for (int k = 1; k < 64; k += 2) all0 &= (ei32[k] == 0);
        g_idx64 = all0;
    }
    if (i < N_NODES) g_cnt[i] = 0;
}
__global__ void hist_kernel(const void* __restrict__ ei) {
    int e = blockIdx.x * blockDim.x + threadIdx.x;
    if (e < N_EDGES) atomicAdd(&g_cnt[edge_dst(ei, e)], 1);
}
__global__ void scan_block_kernel() {
    __shared__ int sb[2][SCAN_B];
    int tid = threadIdx.x;
    int i = blockIdx.x * SCAN_B + tid;
    int v = (i < N_NODES) ? g_cnt[i] : 0;
    sb[0][tid] = v;
    int cur = 0;
#pragma unroll
    for (int d = 1; d < SCAN_B; d <<= 1) {
        __syncthreads();
        int nv = sb[cur][tid] + (tid >= d ? sb[cur][tid - d] : 0);
        sb[cur ^ 1][tid] = nv;
        cur ^= 1;
    }
    __syncthreads();
    if (i < N_NODES) g_rowptr[i + 1] = sb[cur][tid];
    if (tid == SCAN_B - 1) g_bsum[blockIdx.x] = sb[cur][tid];
    if (i == 0) g_rowptr[0] = 0;
}
__global__ void scan_bsum_kernel(int nblocks) {
    __shared__ int sm2[2][128];
    int tid = threadIdx.x;
    int v = (tid < nblocks) ? g_bsum[tid] : 0;
    sm2[0][tid] = v;
    int cur = 0;
#pragma unroll
    for (int d = 1; d < 128; d <<= 1) {
        __syncthreads();
        int nv = sm2[cur][tid] + (tid >= d ? sm2[cur][tid - d] : 0);
        sm2[cur ^ 1][tid] = nv;
        cur ^= 1;
    }
    __syncthreads();
    if (tid < nblocks) g_boff[tid] = sm2[cur][tid] - v;
}
__global__ void finalize_csr_kernel() {
    int i = blockIdx.x * blockDim.x + threadIdx.x;
    if (i >= N_NODES) return;
    int off = g_boff[i / SCAN_B];
    int end = g_rowptr[i + 1] + off;
    g_rowptr[i + 1] = end;
    int c = g_cnt[i];
    g_fill[i] = end - c;
    g_invdeg[i] = 1.0f / fmaxf((float)c, 1.0f);
}
__global__ void fill_kernel(const void* __restrict__ ei) {
    int e = blockIdx.x * blockDim.x + threadIdx.x;
    if (e >= N_EDGES) return;
    int d = edge_dst(ei, e);
    int pos = atomicAdd(&g_fill[d], 1);
    g_srcs[pos] = edge_src(ei, e);
}

// ---------------- persistent dual GEMM, DO=128: Yl fp8 (smem-staged), Yr bf16 ----------------
template <typename TIN>
__launch_bounds__(256, 2)
__global__ void gemm128_dual_kernel(const TIN* __restrict__ X,
                                    const uint32_t* __restrict__ wpl, const uint32_t* __restrict__ wpr,
                                    uint8_t* __restrict__ Ylq, __nv_bfloat16* __restrict__ Yrb) {
    constexpr int S = 68;
    constexpr int ABUF = 64 * S;
    extern __shared__ uint32_t sm[];
    uint32_t* As0 = sm;
    uint32_t* As1 = sm + ABUF;
    uint32_t* Bls = sm + 2 * ABUF;
    uint32_t* Brs = Bls + 128 * S;
    uint8_t*  Stg = (uint8_t*)(Brs + 128 * S);   // 64 x 128 B fp8 staging

    const int t = threadIdx.x;
    const int w = t >> 5;
    const int lane = t & 31;
    const int g = lane >> 2, tg = lane & 3;

#pragma unroll
    for (int it = 0; it < 8; ++it) {
        int i4 = t + it * 256;
        int n = i4 >> 4, kp4 = (i4 & 15) * 4;
        *(uint4*)(Bls + n * S + kp4) = ((const uint4*)wpl)[i4];
        *(uint4*)(Brs + n * S + kp4) = ((const uint4*)wpr)[i4];
    }

    auto fill_A = [&](uint32_t* As, int m0) {
        if constexpr (sizeof(TIN) == 4) {
#pragma unroll
            for (int it = 0; it < 8; ++it) {
                int idx = t + it * 256;
                int row = idx >> 5, c4 = idx & 31;
                int gr  = m0 + row;
                float4 v = make_float4(0.f, 0.f, 0.f, 0.f);
                if (gr < N_NODES) v = *(const float4*)((const float*)X + (size_t)gr * 128 + c4 * 4);
                uint32_t* p = As + row * S + c4 * 2;
                p[0] = pack_bf16(v.x, v.y);
                p[1] = pack_bf16(v.z, v.w);
            }
        } else {
#pragma unroll
            for (int it = 0; it < 4; ++it) {
                int idx = t + it * 256;
                int row = idx >> 4, q = idx & 15;
                int gr  = m0 + row;
                uint4 v = make_uint4(0, 0, 0, 0);
                if (gr < N_NODES) v = ((const uint4*)X)[(size_t)gr * 16 + q];
                *(uint4*)(As + row * S + q * 4) = v;
            }
        }
    };

    if ((int)blockIdx.x < TILES128) fill_A(As0, blockIdx.x * 64);
    __syncthreads();

    const int mgrp = w & 1;
    const int ngrp = (w >> 1) & 1;
    const int isR  = w >> 2;
    const int mr = mgrp * 32;
    const int nb = ngrp * 64;

    const uint32_t a_lane_off = ((mr + (lane & 7) + ((lane >> 3) & 1) * 8) * S + ((lane >> 4) << 2)) * 4;
    // x4 B addressing: lanes 0-7 -> tile 2j rows @k-lo, 8-15 -> @k-hi, 16-23 -> tile 2j+1 @k-lo, 24-31 -> @k-hi
    const uint32_t b_lane4 = ((nb + (lane & 7) + ((lane >> 4) << 3)) * S + (((lane >> 3) & 1) << 2)) * 4;
    const uint32_t bs_base = smem_u32(isR ? Brs : Bls) + b_lane4;
    const uint32_t as0 = smem_u32(As0);
    const uint32_t as1 = smem_u32(As1);

    int buf = 0;
    for (int tile = blockIdx.x; tile < TILES128; tile += GEMM_GRID, buf ^= 1) {
        const int m0 = tile * 64;
        const uint32_t as_base = (buf ? as1 : as0) + a_lane_off;

        float acc[2][8][4];
#pragma unroll
        for (int m = 0; m < 2; ++m)
#pragma unroll
            for (int n = 0; n < 8; ++n)
#pragma unroll
                for (int q = 0; q < 4; ++q) acc[m][n][q] = 0.f;

#pragma unroll
        for (int kt = 0; kt < 8; ++kt) {
            const uint32_t kb = kt * 32;
            uint32_t a0[4], a1[4];
            ldsm_x4(a0, as_base + kb);
            ldsm_x4(a1, as_base + 16 * S * 4 + kb);
#pragma unroll
            for (int jp = 0; jp < 4; ++jp) {   // n-tile pairs (2jp, 2jp+1)
                uint32_t b[4];
                ldsm_x4(b, bs_base + jp * (16 * S * 4) + kb);
                mma_bf16(acc[0][2 * jp],     a0, b + 0);
                mma_bf16(acc[1][2 * jp],     a1, b + 0);
                mma_bf16(acc[0][2 * jp + 1], a0, b + 2);
                mma_bf16(acc[1][2 * jp + 1], a1, b + 2);
            }
        }

        int nt = tile + GEMM_GRID;
        if (nt < TILES128) fill_A(buf ? As0 : As1, nt * 64);

        if (!isR) {
#pragma unroll
            for (int m = 0; m < 2; ++m) {
                const int lr0 = mr + m * 16 + g;
#pragma unroll
                for (int n = 0; n < 8; ++n) {
                    int col = nb + n * 8 + 2 * tg;
                    *(uint16_t*)(Stg + lr0 * 128 + col)       = pack_e4m3(acc[m][n][0], acc[m][n][1]);
                    *(uint16_t*)(Stg + (lr0 + 8) * 128 + col) = pack_e4m3(acc[m][n][2], acc[m][n][3]);
                }
            }
            asm volatile("bar.sync 1, 128;" ::: "memory");
#pragma unroll
            for (int it = 0; it < 4; ++it) {
                int i4 = t + it * 128;
                int row = i4 >> 3, q = i4 & 7;
                int gr = m0 + row;
                if (gr < N_NODES)
                    *(uint4*)(Ylq + (size_t)gr * 128 + q * 16) = *(const uint4*)(Stg + row * 128 + q * 16);
            }
        } else {
#pragma unroll
            for (int m = 0; m < 2; ++m) {
                const int r0 = m0 + mr + m * 16 + g;
                const int r1 = r0 + 8;
#pragma unroll
                for (int n = 0; n < 8; ++n) {
                    int col = nb + n * 8 + 2 * tg;
                    if (r0 < N_NODES)
                        *(uint32_t*)((char*)Yrb + (size_t)r0 * 256 + col * 2) = pack_bf16(acc[m][n][0], acc[m][n][1]);
                    if (r1 < N_NODES)
                        *(uint32_t*)((char*)Yrb + (size_t)r1 * 256 + col * 2) = pack_bf16(acc[m][n][2], acc[m][n][3]);
                }
            }
        }
        __syncthreads();
    }
}

// ---------------- dual GEMM, DO=32: Yl bf16, Yr fp32 ----------------
__launch_bounds__(256, 2)
__global__ void gemm32_dual_kernel(const __nv_bfloat16* __restrict__ X,
                                   const uint32_t* __restrict__ wpl, const uint32_t* __restrict__ wpr,
                                   __nv_bfloat16* __restrict__ Ylb, float* __restrict__ Yr) {
    constexpr int S = 68;
    extern __shared__ uint32_t sm[];
    uint32_t* As  = sm;
    uint32_t* Bls = sm + 128 * S;
    uint32_t* Brs = Bls + 32 * S;

    const int t = threadIdx.x;
    const int w = t >> 5;
    const int lane = t & 31;
    const int g = lane >> 2, tg = lane & 3;
    const int m0 = blockIdx.x * 128;

#pragma unroll
    for (int it = 0; it < 8; ++it) {
        int idx = t + it * 256;
        int row = idx >> 4, q = idx & 15;
        int gr  = m0 + row;
        uint4 v = make_uint4(0, 0, 0, 0);
        if (gr < N_NODES) v = ((const uint4*)X)[(size_t)gr * 16 + q];
        *(uint4*)(As + row * S + q * 4) = v;
    }
#pragma unroll
    for (int it = 0; it < 2; ++it) {
        int i4 = t + it * 256;
        int n = i4 >> 4, kp4 = (i4 & 15) * 4;
        *(uint4*)(Bls + n * S + kp4) = ((const uint4*)wpl)[i4];
        *(uint4*)(Brs + n * S + kp4) = ((const uint4*)wpr)[i4];
    }
    __syncthreads();

    const int mr = w * 16;
    float accl[4][4], accr[4][4];
#pragma unroll
    for (int n = 0; n < 4; ++n)
#pragma unroll
        for (int q = 0; q < 4; ++q) { accl[n][q] = 0.f; accr[n][q] = 0.f; }

#pragma unroll
    for (int kt = 0; kt < 8; ++kt) {
        const int kb = kt * 8;
        uint32_t a[4];
        a[0] = As[(mr + g)     * S + kb + tg];
        a[1] = As[(mr + g + 8) * S + kb + tg];
        a[2] = As[(mr + g)     * S + kb + tg + 4];
        a[3] = As[(mr + g + 8) * S + kb + tg + 4];
#pragma unroll
        for (int n = 0; n < 4; ++n) {
            int col = n * 8 + g;
            uint32_t bl[2], br[2];
            bl[0] = Bls[col * S + kb + tg];
            bl[1] = Bls[col * S + kb + tg + 4];
            br[0] = Brs[col * S + kb + tg];
            br[1] = Brs[col * S + kb + tg + 4];
            mma_bf16(accl[n], a, bl);
            mma_bf16(accr[n], a, br);
        }
    }

    const int r0 = m0 + mr + g;
    const int r1 = r0 + 8;
#pragma unroll
    for (int n = 0; n < 4; ++n) {
        int col = n * 8 + 2 * tg;
        if (r0 < N_NODES) {
            *(uint32_t*)((char*)Ylb + (size_t)r0 * 64 + col * 2) = pack_bf16(accl[n][0], accl[n][1]);
            *(float2*)(Yr + (size_t)r0 * 32 + col) = make_float2(accr[n][0], accr[n][1]);
        }
        if (r1 < N_NODES) {
            *(uint32_t*)((char*)Ylb + (size_t)r1 * 64 + col * 2) = pack_bf16(accl[n][2], accl[n][3]);
            *(float2*)(Yr + (size_t)r1 * 32 + col) = make_float2(accr[n][2], accr[n][3]);
        }
    }
}

// ---------------- aggregation: fp8 gather (2 edges/warp), half2 accumulation ----------------
__global__ void agg_relu_kernel(const uint8_t* __restrict__ ylq, const __nv_bfloat16* __restrict__ yrb,
                                const float* __restrict__ bl, __nv_bfloat16* __restrict__ hb) {
    int node = blockIdx.x * (blockDim.x >> 5) + (threadIdx.x >> 5);
    if (node >= N_NODES) return;
    int lane = threadIdx.x & 31;
    int g2 = lane >> 4;
    int p  = lane & 15;
    int beg = g_rowptr[node], end = g_rowptr[node + 1];
    uint32_t h0a = 0, h1a = 0, h2a = 0, h3a = 0;
    int j = beg;
    for (; j + 8 <= end; j += 8) {
        uint2 u[4];
#pragma unroll
        for (int q = 0; q < 4; ++q) {
            int s = __ldg(&g_srcs[j + 2 * q + g2]);
            u[q] = *(const uint2*)(ylq + (size_t)s * 128 + p * 8);
        }
#pragma unroll
        for (int q = 0; q < 4; ++q) {
            h0a = hadd2(h0a, fp8x2_to_h2(u[q].x & 0xFFFFu));
            h1a = hadd2(h1a, fp8x2_to_h2(u[q].x >> 16));
            h2a = hadd2(h2a, fp8x2_to_h2(u[q].y & 0xFFFFu));
            h3a = hadd2(h3a, fp8x2_to_h2(u[q].y >> 16));
        }
    }
    for (; j + 2 <= end; j += 2) {
        int s = __ldg(&g_srcs[j + g2]);
        uint2 u = *(const uint2*)(ylq + (size_t)s * 128 + p * 8);
        h0a = hadd2(h0a, fp8x2_to_h2(u.x & 0xFFFFu));
        h1a = hadd2(h1a, fp8x2_to_h2(u.x >> 16));
        h2a = hadd2(h2a, fp8x2_to_h2(u.y & 0xFFFFu));
        h3a = hadd2(h3a, fp8x2_to_h2(u.y >> 16));
    }
    if (j < end && g2 == 0) {
        int s = __ldg(&g_srcs[j]);
        uint2 u = *(const uint2*)(ylq + (size_t)s * 128 + p * 8);
        h0a = hadd2(h0a, fp8x2_to_h2(u.x & 0xFFFFu));
        h1a = hadd2(h1a, fp8x2_to_h2(u.x >> 16));
        h2a = hadd2(h2a, fp8x2_to_h2(u.y & 0xFFFFu));
        h3a = hadd2(h3a, fp8x2_to_h2(u.y >> 16));
    }
    h0a = hadd2(h0a, __shfl_xor_sync(0xFFFFFFFFu, h0a, 16));
    h1a = hadd2(h1a, __shfl_xor_sync(0xFFFFFFFFu, h1a, 16));
    h2a = hadd2(h2a, __shfl_xor_sync(0xFFFFFFFFu, h2a, 16));
    h3a = hadd2(h3a, __shfl_xor_sync(0xFFFFFFFFu, h3a, 16));

    if (g2 == 0) {
        float2 a01 = h2f2(h0a), a23 = h2f2(h1a), a45 = h2f2(h2a), a67 = h2f2(h3a);
        float id = g_invdeg[node];
        uint4 ur = *(const uint4*)((const char*)yrb + (size_t)node * 256 + p * 16);
        float2 r01 = __bfloat1622float2(*(__nv_bfloat162*)&ur.x);
        float2 r23 = __bfloat1622float2(*(__nv_bfloat162*)&ur.y);
        float2 r45 = __bfloat1622float2(*(__nv_bfloat162*)&ur.z);
        float2 r67 = __bfloat1622float2(*(__nv_bfloat162*)&ur.w);
        float4 b0 = ((const float4*)bl)[2 * p];
        float4 b1 = ((const float4*)bl)[2 * p + 1];
        float o0 = fmaxf(fmaf(a01.x, id, b0.x) + r01.x, 0.f);
        float o1 = fmaxf(fmaf(a01.y, id, b0.y) + r01.y, 0.f);
        float o2 = fmaxf(fmaf(a23.x, id, b0.z) + r23.x, 0.f);
        float o3 = fmaxf(fmaf(a23.y, id, b0.w) + r23.y, 0.f);
        float o4 = fmaxf(fmaf(a45.x, id, b1.x) + r45.x, 0.f);
        float o5 = fmaxf(fmaf(a45.y, id, b1.y) + r45.y, 0.f);
        float o6 = fmaxf(fmaf(a67.x, id, b1.z) + r67.x, 0.f);
        float o7 = fmaxf(fmaf(a67.y, id, b1.w) + r67.y, 0.f);
        uint4 ov = make_uint4(pack_bf16(o0, o1), pack_bf16(o2, o3),
                              pack_bf16(o4, o5), pack_bf16(o6, o7));
        *(uint4*)((char*)hb + (size_t)node * 256 + p * 16) = ov;
    }
}

// log_softmax layer: yl bf16 [N,32]; 2 edges per warp
__global__ void agg_lsm_kernel(const __nv_bfloat16* __restrict__ ylb, const float* __restrict__ yr,
                               const float* __restrict__ bl2, float* __restrict__ out) {
    int node = blockIdx.x * (blockDim.x >> 5) + (threadIdx.x >> 5);
    if (node >= N_NODES) return;
    int lane = threadIdx.x & 31;
    int g2 = lane >> 4;
    int p  = lane & 15;
    int beg = g_rowptr[node], end = g_rowptr[node + 1];
    float ax = 0.f, ay = 0.f;
    const uint32_t* yl32 = (const uint32_t*)ylb;
    int j = beg;
    for (; j + 4 <= end; j += 4) {
        int sA = __ldg(&g_srcs[j + g2]);
        int sB = __ldg(&g_srcs[j + 2 + g2]);
        uint32_t uA = __ldg(&yl32[(size_t)sA * 16 + p]);
        uint32_t uB = __ldg(&yl32[(size_t)sB * 16 + p]);
        float2 fA = __bfloat1622float2(*(__nv_bfloat162*)&uA);
        float2 fB = __bfloat1622float2(*(__nv_bfloat162*)&uB);
        ax += fA.x + fB.x; ay += fA.y + fB.y;
    }
    if (j + 2 <= end) {
        int s = __ldg(&g_srcs[j + g2]);
        uint32_t u = __ldg(&yl32[(size_t)s * 16 + p]);
        float2 f = __bfloat1622float2(*(__nv_bfloat162*)&u);
        ax += f.x; ay += f.y;
        j += 2;
    }
    if (j < end && g2 == 0) {
        int s = __ldg(&g_srcs[j]);
        uint32_t u = __ldg(&yl32[(size_t)s * 16 + p]);
        float2 f = __bfloat1622float2(*(__nv_bfloat162*)&u);
        ax += f.x; ay += f.y;
    }
    ax += __shfl_xor_sync(0xFFFFFFFFu, ax, 16);
    ay += __shfl_xor_sync(0xFFFFFFFFu, ay, 16);

    float id = g_invdeg[node];
    float2 b2 = ((const float2*)bl2)[p];
    float2 r2 = ((const float2*)yr)[(size_t)node * 16 + p];
    float v0 = fmaf(ax, id, b2.x) + r2.x;
    float v1 = fmaf(ay, id, b2.y) + r2.y;
    float m = fmaxf(v0, v1);
#pragma unroll
    for (int o = 1; o < 16; o <<= 1) m = fmaxf(m, __shfl_xor_sync(0xFFFFFFFFu, m, o));
    float s = expf(v0 - m) + expf(v1 - m);
#pragma unroll
    for (int o = 1; o < 16; o <<= 1) s += __shfl_xor_sync(0xFFFFFFFFu, s, o);
    float ls = logf(s);
    if (g2 == 0)
        ((float2*)out)[(size_t)node * 16 + p] = make_float2(v0 - m - ls, v1 - m - ls);
}

// ---------------- host ----------------
extern "C" void kernel_launch(void* const* d_in, const int* in_sizes, int n_in,
                              void* d_out, int out_size) {
    const float* x   = (const float*)d_in[0];
    const void*  ei  = d_in[1];
    const float* Wl0 = (const float*)d_in[2];
    const float* bl0 = (const float*)d_in[3];
    const float* Wr0 = (const float*)d_in[4];
    const float* Wl1 = (const float*)d_in[5];
    const float* bl1 = (const float*)d_in[6];
    const float* Wr1 = (const float*)d_in[7];
    const float* Wl2 = (const float*)d_in[8];
    const float* bl2 = (const float*)d_in[9];
    const float* Wr2 = (const float*)d_in[10];
    float* out = (float*)d_out;

    float *yl, *yr, *h0;
    uint32_t *wp128, *wp32;
    cudaGetSymbolAddress((void**)&yl, g_yl);
    cudaGetSymbolAddress((void**)&yr, g_yr);
    cudaGetSymbolAddress((void**)&h0, g_h0);
    cudaGetSymbolAddress((void**)&wp128, g_wp128);
    cudaGetSymbolAddress((void**)&wp32, g_wp32);
    uint8_t*       ylq = (uint8_t*)yl;
    __nv_bfloat16* ylb = (__nv_bfloat16*)yl;
    __nv_bfloat16* yrb = (__nv_bfloat16*)yr;
    __nv_bfloat16* h0b = (__nv_bfloat16*)h0;

    static cudaStream_t s2 = nullptr;
    static cudaEvent_t ev_fork = nullptr, ev_join = nullptr;
    if (!s2) {
        cudaStreamCreateWithFlags(&s2, cudaStreamNonBlocking);
        cudaEventCreateWithFlags(&ev_fork, cudaEventDisableTiming);
        cudaEventCreateWithFlags(&ev_join, cudaEventDisableTiming);
    }

    const int SMEM128 = (2 * 64 * 68 + 2 * 128 * 68) * 4 + 64 * 128;  // 112640
    const int SMEM32  = (128 * 68 + 2 * 32 * 68) * 4;
    cudaFuncSetAttribute(gemm128_dual_kernel<float>, cudaFuncAttributeMaxDynamicSharedMemorySize, SMEM128);
    cudaFuncSetAttribute(gemm128_dual_kernel<__nv_bfloat16>, cudaFuncAttributeMaxDynamicSharedMemorySize, SMEM128);
    cudaFuncSetAttribute(gemm32_dual_kernel, cudaFuncAttributeMaxDynamicSharedMemorySize, SMEM32);

    const int T = 256;
    const int NB = (N_NODES + T - 1) / T;
    const int EB = (N_EDGES + T - 1) / T;
    const int SCB = (N_NODES + SCAN_B - 1) / SCAN_B;
    const int AGG_B = (N_NODES + 7) / 8;
    const int GT32 = (N_NODES + 127) / 128;

    // front: CSR on s2 overlapped with pack + layer-0 GEMM on main (gemm = submission #4)
    cudaEventRecord(ev_fork, 0);
    cudaStreamWaitEvent(s2, ev_fork, 0);

    init_kernel<<<NB, T, 0, s2>>>((const int*)ei);                               // #1
    pack_w_kernel<<<144, 256>>>(Wl0, Wr0, Wl1, Wr1, Wl2, Wr2);                   // #2 (main)
    hist_kernel<<<EB, T, 0, s2>>>(ei);                                           // #3
    gemm128_dual_kernel<float><<<GEMM_GRID, 256, SMEM128>>>(x, wp128, wp128 + 8192, ylq, yrb);  // #4 (main)
    scan_block_kernel<<<SCB, SCAN_B, 0, s2>>>();                                 // #5
    scan_bsum_kernel<<<1, 128, 0, s2>>>(SCB);                                    // #6
    finalize_csr_kernel<<<NB, T, 0, s2>>>();                                     // #7
    fill_kernel<<<EB, T, 0, s2>>>(ei);                                           // #8
    cudaEventRecord(ev_join, s2);
    cudaStreamWaitEvent(0, ev_join, 0);

    // ---- Layer 0 aggregation ----
    agg_relu_kernel<<<AGG_B, T>>>(ylq, yrb, bl0, h0b);
    // ---- Layer 1 ----
    gemm128_dual_kernel<__nv_bfloat16><<<GEMM_GRID, 256, SMEM128>>>(h0b, wp128 + 2 * 8192, wp128 + 3 * 8192, ylq, yrb);
    agg_relu_kernel<<<AGG_B, T>>>(ylq, yrb, bl1, h0b);
    // ---- Layer 2 ----
    gemm32_dual_kernel<<<GT32, T, SMEM32>>>(h0b, wp32, wp32 + 2048, ylb, yr);
    agg_lsm_kernel<<<AGG_B, T>>>(ylb, yr, bl2, out);
}